// round 1
// baseline (speedup 1.0000x reference)
#include <cuda_runtime.h>
#include <math.h>

#define HH 128
#define WW 128
#define HWp (HH*WW)          // 16384
#define Cin 64
#define Cout 64
#define Bsz 2
#define NPIX (Bsz*HWp)       // 32768

// Scratch (no allocations allowed)
__device__ float g_om[Bsz*27*HWp];     // 18 raw offsets + 9 sigmoided masks
__device__ float g_wT[9*Cin*Cout];     // conv_w transposed to [k][c][o]
__device__ float g_tmp[Bsz*Cout*HWp];  // pre-BN conv output
__device__ float g_bn[2*Cout];         // scale, shift

// ---------------------------------------------------------------------------
// kW: transpose conv_w [o][c][k] -> [k][c][o] (coalesced reads, one-shot)
// ---------------------------------------------------------------------------
__global__ void kW(const float* __restrict__ w)
{
    int i = blockIdx.x * 256 + threadIdx.x;
    if (i >= Cout * Cin * 9) return;
    int o = i / (Cin * 9);
    int r = i - o * (Cin * 9);
    int c = r / 9;
    int k = r - c * 9;
    g_wT[(k * Cin + c) * Cout + o] = w[i];
}

// ---------------------------------------------------------------------------
// kA: fused 27-channel 3x3 conv (18 offset + 9 mask, sigmoid on mask)
// 1 thread = 1 pixel. Weights in smem transposed to [c*9+t][28] for LDS.128.
// ---------------------------------------------------------------------------
__global__ __launch_bounds__(128) void kA(
    const float* __restrict__ x,
    const float* __restrict__ off_w, const float* __restrict__ off_b,
    const float* __restrict__ mask_w, const float* __restrict__ mask_b)
{
    extern __shared__ float ws[];   // [576][28] = 64512 bytes
    int tid = threadIdx.x;
    for (int i = tid; i < 27 * 576; i += 128) {
        int oc = i / 576;
        int ct = i - oc * 576;
        float v = (oc < 18) ? off_w[i] : mask_w[(oc - 18) * 576 + ct];
        ws[ct * 28 + oc] = v;
    }
    __syncthreads();

    int p  = blockIdx.x * 128 + tid;
    int b  = p >> 14;
    int yx = p & (HWp - 1);
    int y  = yx >> 7;
    int xx = yx & (WW - 1);
    const float* xb = x + b * Cin * HWp;

    float acc[28];
#pragma unroll
    for (int j = 0; j < 18; j++) acc[j] = off_b[j];
#pragma unroll
    for (int j = 0; j < 9; j++)  acc[18 + j] = mask_b[j];
    acc[27] = 0.f;

    for (int c = 0; c < Cin; c++) {
        const float* xc = xb + c * HWp;
#pragma unroll
        for (int t = 0; t < 9; t++) {
            int yy  = y + t / 3 - 1;
            int xx2 = xx + t % 3 - 1;
            float xv = ((unsigned)yy < HH && (unsigned)xx2 < WW) ? xc[yy * WW + xx2] : 0.f;
            const float4* wr = (const float4*)(ws + (c * 9 + t) * 28);
#pragma unroll
            for (int j4 = 0; j4 < 7; j4++) {
                float4 w4 = wr[j4];
                acc[j4 * 4 + 0] += xv * w4.x;
                acc[j4 * 4 + 1] += xv * w4.y;
                acc[j4 * 4 + 2] += xv * w4.z;
                acc[j4 * 4 + 3] += xv * w4.w;
            }
        }
    }

    float* omb = g_om + b * 27 * HWp;
#pragma unroll
    for (int j = 0; j < 18; j++) omb[j * HWp + yx] = acc[j];
#pragma unroll
    for (int j = 0; j < 9; j++)
        omb[(18 + j) * HWp + yx] = 1.f / (1.f + expf(-acc[18 + j]));
}

// ---------------------------------------------------------------------------
// kB: deformable conv core. 1 thread = 1 pixel, 64 fp32 accumulators.
// Per tap: bilinear weights (validity-masked as in reference), then for each
// input channel: 4 gathers -> v, broadcast-FMA into 64 outputs (weights via
// float4 from smem, slice [c][o] reloaded per tap).
// ---------------------------------------------------------------------------
__global__ __launch_bounds__(128, 4) void kB(const float* __restrict__ x)
{
    __shared__ float ws[Cin * Cout];   // 16 KB, per-tap slice [c][o]
    int tid = threadIdx.x;
    int p  = blockIdx.x * 128 + tid;
    int b  = p >> 14;
    int yx = p & (HWp - 1);
    int y  = yx >> 7;
    int xx = yx & (WW - 1);
    const float* xb  = x + b * Cin * HWp;
    const float* omb = g_om + b * 27 * HWp;

    float acc[64];
#pragma unroll
    for (int o = 0; o < 64; o++) acc[o] = 0.f;

    for (int k = 0; k < 9; k++) {
        __syncthreads();
        for (int i = tid; i < Cin * Cout; i += 128)
            ws[i] = g_wT[k * Cin * Cout + i];
        __syncthreads();

        float ofy = omb[(2 * k) * HWp + yx];
        float ofx = omb[(2 * k + 1) * HWp + yx];
        float m   = omb[(18 + k) * HWp + yx];

        float py = ofy + (float)y  + (float)(k / 3) - 1.f;
        float px = ofx + (float)xx + (float)(k % 3) - 1.f;
        float fy = floorf(py), fx = floorf(px);
        int   y0 = (int)fy,    x0 = (int)fx;
        float wy1 = py - fy, wx1 = px - fx;
        float wy0 = 1.f - wy1, wx0 = 1.f - wx1;

        bool vy0 = ((unsigned)y0 < HH),       vy1 = ((unsigned)(y0 + 1) < HH);
        bool vx0 = ((unsigned)x0 < WW),       vx1 = ((unsigned)(x0 + 1) < WW);
        int cy0 = min(max(y0, 0), HH - 1),    cy1 = min(max(y0 + 1, 0), HH - 1);
        int cx0 = min(max(x0, 0), WW - 1),    cx1 = min(max(x0 + 1, 0), WW - 1);

        float w00 = (vy0 && vx0) ? wy0 * wx0 * m : 0.f;
        float w01 = (vy0 && vx1) ? wy0 * wx1 * m : 0.f;
        float w10 = (vy1 && vx0) ? wy1 * wx0 * m : 0.f;
        float w11 = (vy1 && vx1) ? wy1 * wx1 * m : 0.f;

        int o00 = cy0 * WW + cx0, o01 = cy0 * WW + cx1;
        int o10 = cy1 * WW + cx0, o11 = cy1 * WW + cx1;

        const float* xc = xb;
        for (int c = 0; c < Cin; c++) {
            float v = w00 * xc[o00] + w01 * xc[o01] + w10 * xc[o10] + w11 * xc[o11];
            const float4* wr = (const float4*)(ws + (c << 6));
#pragma unroll
            for (int o4 = 0; o4 < 16; o4++) {
                float4 w4 = wr[o4];
                acc[o4 * 4 + 0] += v * w4.x;
                acc[o4 * 4 + 1] += v * w4.y;
                acc[o4 * 4 + 2] += v * w4.z;
                acc[o4 * 4 + 3] += v * w4.w;
            }
            xc += HWp;
        }
    }

    float* tb = g_tmp + b * Cout * HWp;
#pragma unroll
    for (int o = 0; o < 64; o++) tb[o * HWp + yx] = acc[o];
}

// ---------------------------------------------------------------------------
// kC: per-channel mean/var over (B,H,W), produce scale/shift
// ---------------------------------------------------------------------------
__global__ void kC(const float* __restrict__ gamma, const float* __restrict__ beta)
{
    __shared__ float ss[256], sq[256];
    int c = blockIdx.x, tid = threadIdx.x;
    float s = 0.f, q = 0.f;
    for (int b = 0; b < Bsz; b++) {
        const float* t = g_tmp + (b * Cout + c) * HWp;
        for (int i = tid; i < HWp; i += 256) { float v = t[i]; s += v; q += v * v; }
    }
    ss[tid] = s; sq[tid] = q;
    __syncthreads();
    for (int st = 128; st > 0; st >>= 1) {
        if (tid < st) { ss[tid] += ss[tid + st]; sq[tid] += sq[tid + st]; }
        __syncthreads();
    }
    if (tid == 0) {
        float n = (float)(Bsz * HWp);
        float mean = ss[0] / n;
        float var  = sq[0] / n - mean * mean;
        float sc = gamma[c] * rsqrtf(var + 1e-5f);
        g_bn[c] = sc;
        g_bn[Cout + c] = beta[c] - mean * sc;
    }
}

// ---------------------------------------------------------------------------
// kD: elementwise BN affine + ReLU (float4)
// ---------------------------------------------------------------------------
__global__ void kD(float* __restrict__ out)
{
    int i = blockIdx.x * 256 + threadIdx.x;      // over 524288 float4s
    const float4* t4 = (const float4*)g_tmp;
    float4 v = t4[i];
    int c = (i >> 12) & 63;                      // (i*4 / HW) % 64
    float sc = g_bn[c], sh = g_bn[Cout + c];
    float4 r;
    r.x = fmaxf(v.x * sc + sh, 0.f);
    r.y = fmaxf(v.y * sc + sh, 0.f);
    r.z = fmaxf(v.z * sc + sh, 0.f);
    r.w = fmaxf(v.w * sc + sh, 0.f);
    ((float4*)out)[i] = r;
}

// ---------------------------------------------------------------------------
extern "C" void kernel_launch(void* const* d_in, const int* in_sizes, int n_in,
                              void* d_out, int out_size)
{
    const float* x      = (const float*)d_in[0];
    const float* conv_w = (const float*)d_in[1];
    const float* off_w  = (const float*)d_in[2];
    const float* off_b  = (const float*)d_in[3];
    const float* mask_w = (const float*)d_in[4];
    const float* mask_b = (const float*)d_in[5];
    const float* gamma  = (const float*)d_in[6];
    const float* beta   = (const float*)d_in[7];
    float* out = (float*)d_out;

    cudaFuncSetAttribute(kA, cudaFuncAttributeMaxDynamicSharedMemorySize, 27 * 576 * 4 + 576 * 4);

    kW<<<(Cout * Cin * 9 + 255) / 256, 256>>>(conv_w);
    kA<<<NPIX / 128, 128, 576 * 28 * 4>>>(x, off_w, off_b, mask_w, mask_b);
    kB<<<NPIX / 128, 128>>>(x);
    kC<<<Cout, 256>>>(gamma, beta);
    kD<<<(Bsz * Cout * HWp / 4) / 256, 256>>>(out);
}

// round 3
// speedup vs baseline: 1.2034x; 1.2034x over previous
#include <cuda_runtime.h>
#include <cstdint>
#include <math.h>

#define HH 128
#define WW 128
#define HWp 16384
#define Cin 64
#define Cout 64
#define Bsz 2
#define NPIX 32768

// ---------------------------------------------------------------------------
// Scratch (no allocations allowed)
// ---------------------------------------------------------------------------
__device__ float  g_om[Bsz*27*HWp];     // 18 raw offsets + 9 sigmoided masks
__device__ float2 g_wFh[9*8*8*32];      // kB B-frags hi: [tap][ks][nt][lane]
__device__ float2 g_wFl[9*8*8*32];      // kB B-frags lo
__device__ float2 g_wAF[9*8*4*32];      // kA B-frags:    [tap][ks][nt4][lane]
__device__ float  g_tmp[Bsz*Cout*HWp];  // pre-BN conv output (NCHW)
__device__ float  g_bn[2*Cout];         // scale, shift

// ---------------------------------------------------------------------------
__device__ __forceinline__ uint32_t cvt_tf32(float v) {
    uint32_t r;
    asm("cvt.rna.tf32.f32 %0, %1;" : "=r"(r) : "f"(v));
    return r;
}
__device__ __forceinline__ void mma_t(float* d,
    uint32_t a0, uint32_t a1, uint32_t a2, uint32_t a3,
    uint32_t b0, uint32_t b1)
{
    asm volatile("mma.sync.aligned.m16n8k8.row.col.f32.tf32.tf32.f32 "
        "{%0,%1,%2,%3}, {%4,%5,%6,%7}, {%8,%9}, {%0,%1,%2,%3};"
        : "+f"(d[0]), "+f"(d[1]), "+f"(d[2]), "+f"(d[3])
        : "r"(a0), "r"(a1), "r"(a2), "r"(a3), "r"(b0), "r"(b1));
}

// ---------------------------------------------------------------------------
// kWB: pack conv_w into mma B-fragment layout (hi/lo tf32 split).
// B frag (m16n8k8, col-major B): lane holds (k=lane%4, n=lane/4) and (k+4, n).
// n = output channel o = nt*8 + lane/4 ; k-chunk ks covers c = ks*8 + k.
// ---------------------------------------------------------------------------
__global__ void kWB(const float* __restrict__ w)
{
    int i = blockIdx.x * 256 + threadIdx.x;        // 9*8*8*32 = 18432
    if (i >= 9*8*8*32) return;
    int lane = i & 31;
    int nt   = (i >> 5) & 7;
    int ks   = (i >> 8) & 7;
    int tap  = i >> 11;
    int o  = nt * 8 + (lane >> 2);
    int c0 = ks * 8 + (lane & 3);
    float v0 = w[o * 576 + c0 * 9 + tap];
    float v1 = w[o * 576 + (c0 + 4) * 9 + tap];
    uint32_t h0 = cvt_tf32(v0); float l0 = v0 - __uint_as_float(h0);
    uint32_t h1 = cvt_tf32(v1); float l1 = v1 - __uint_as_float(h1);
    g_wFh[i] = make_float2(__uint_as_float(h0), __uint_as_float(h1));
    g_wFl[i] = make_float2(__uint_as_float(cvt_tf32(l0)), __uint_as_float(cvt_tf32(l1)));
}

// ---------------------------------------------------------------------------
// kWA: pack offset(18)+mask(9) conv weights (padded to n=32) into B-fragments.
// ---------------------------------------------------------------------------
__global__ void kWA(const float* __restrict__ off_w, const float* __restrict__ mask_w)
{
    int i = blockIdx.x * 256 + threadIdx.x;        // 9*8*4*32 = 9216
    if (i >= 9*8*4*32) return;
    int lane = i & 31;
    int nt   = (i >> 5) & 3;
    int ks   = (i >> 7) & 7;
    int tap  = i >> 10;
    int o  = nt * 8 + (lane >> 2);
    int c0 = ks * 8 + (lane & 3);
    float v0 = 0.f, v1 = 0.f;
    if (o < 18) {
        v0 = off_w[o * 576 + c0 * 9 + tap];
        v1 = off_w[o * 576 + (c0 + 4) * 9 + tap];
    } else if (o < 27) {
        v0 = mask_w[(o - 18) * 576 + c0 * 9 + tap];
        v1 = mask_w[(o - 18) * 576 + (c0 + 4) * 9 + tap];
    }
    g_wAF[i] = make_float2(__uint_as_float(cvt_tf32(v0)), __uint_as_float(cvt_tf32(v1)));
}

// ---------------------------------------------------------------------------
// kA3: offset/mask conv as tensor-core GEMM (K=576, N=27 pad 32), 1 tf32 part.
// CTA = one image row (128 px), 8 warps x 16 px.
// ---------------------------------------------------------------------------
__global__ __launch_bounds__(256) void kA3(
    const float* __restrict__ x,
    const float* __restrict__ off_b, const float* __restrict__ mask_b)
{
    int tid = threadIdx.x, wid = tid >> 5, lane = tid & 31;
    int b = blockIdx.x >> 7, y = blockIdx.x & 127;
    int p0 = wid * 16 + (lane >> 2), p1 = p0 + 8;
    const float* xb = x + b * Cin * HWp;

    float acc[4][4];
#pragma unroll
    for (int n = 0; n < 4; n++)
#pragma unroll
        for (int j = 0; j < 4; j++) acc[n][j] = 0.f;

    for (int tap = 0; tap < 9; tap++) {
        int dy = tap / 3 - 1, dx = tap % 3 - 1;
        int yy = y + dy;
        bool vy = ((unsigned)yy < HH);
        int yc = vy ? yy : 0;
        int px0 = p0 + dx, px1 = p1 + dx;
        bool v0 = vy && ((unsigned)px0 < WW);
        bool v1 = vy && ((unsigned)px1 < WW);
        int q0 = v0 ? px0 : 0, q1 = v1 ? px1 : 0;
        const float* xr = xb + yc * WW;
        const float2* bp = g_wAF + (tap * 8) * 4 * 32 + lane;

        for (int ks = 0; ks < 8; ks++) {
            int c0 = ks * 8 + (lane & 3);
            const float* pc0 = xr + c0 * HWp;
            const float* pc1 = pc0 + 4 * HWp;
            uint32_t a0 = cvt_tf32(v0 ? pc0[q0] : 0.f);
            uint32_t a1 = cvt_tf32(v1 ? pc0[q1] : 0.f);
            uint32_t a2 = cvt_tf32(v0 ? pc1[q0] : 0.f);
            uint32_t a3 = cvt_tf32(v1 ? pc1[q1] : 0.f);
            const float2* bq = bp + ks * 4 * 32;
#pragma unroll
            for (int nt = 0; nt < 4; nt++) {
                float2 bv = __ldg(bq + nt * 32);
                mma_t(acc[nt], a0, a1, a2, a3,
                      __float_as_uint(bv.x), __float_as_uint(bv.y));
            }
        }
    }

    float* omb = g_om + b * 27 * HWp;
    int yx0 = y * WW + p0, yx1 = y * WW + p1;
#pragma unroll
    for (int nt = 0; nt < 4; nt++) {
        int o = nt * 8 + (lane & 3) * 2;
#pragma unroll
        for (int j = 0; j < 2; j++) {
            int oc = o + j;
            if (oc < 27) {
                float bias = (oc < 18) ? off_b[oc] : mask_b[oc - 18];
                float r0 = acc[nt][j] + bias;
                float r1 = acc[nt][j + 2] + bias;
                if (oc >= 18) {
                    r0 = 1.f / (1.f + expf(-r0));
                    r1 = 1.f / (1.f + expf(-r1));
                }
                omb[oc * HWp + yx0] = r0;
                omb[oc * HWp + yx1] = r1;
            }
        }
    }
}

// ---------------------------------------------------------------------------
// kB3: fused deformable gather + mma.sync tf32 GEMM (3-term tf32 split).
// CTA = one image row. Warp = 16 pixels (M=16) x 64 outputs (8 n-tiles).
// A fragments gathered straight into registers; B frags via __ldg (L1-hot).
// ---------------------------------------------------------------------------
__global__ __launch_bounds__(256) void kB3(const float* __restrict__ x)
{
    int tid = threadIdx.x, wid = tid >> 5, lane = tid & 31;
    int b = blockIdx.x >> 7, y = blockIdx.x & 127;
    int p0 = wid * 16 + (lane >> 2), p1 = p0 + 8;
    const float* xb  = x + b * Cin * HWp;
    const float* omb = g_om + b * 27 * HWp;
    int yx0 = y * WW + p0, yx1 = y * WW + p1;

    float acc[8][4];
#pragma unroll
    for (int n = 0; n < 8; n++)
#pragma unroll
        for (int j = 0; j < 4; j++) acc[n][j] = 0.f;

    for (int tap = 0; tap < 9; tap++) {
        // ---- bilinear setup for both pixels ----
        float wA[4], wB[4];
        int   oA[4], oB[4];
#pragma unroll
        for (int s = 0; s < 2; s++) {
            int yx = s ? yx1 : yx0;
            int px = s ? p1 : p0;
            float ofy = omb[(2 * tap) * HWp + yx];
            float ofx = omb[(2 * tap + 1) * HWp + yx];
            float m   = omb[(18 + tap) * HWp + yx];
            float py = ofy + (float)y  + (float)(tap / 3) - 1.f;
            float pxx = ofx + (float)px + (float)(tap % 3) - 1.f;
            float fy = floorf(py), fx = floorf(pxx);
            int   y0 = (int)fy,    x0 = (int)fx;
            float wy1 = py - fy,  wx1 = pxx - fx;
            float wy0 = 1.f - wy1, wx0 = 1.f - wx1;
            bool vy0 = ((unsigned)y0 < HH),      vy1 = ((unsigned)(y0 + 1) < HH);
            bool vx0 = ((unsigned)x0 < WW),      vx1 = ((unsigned)(x0 + 1) < WW);
            int cy0 = min(max(y0, 0), HH - 1),   cy1 = min(max(y0 + 1, 0), HH - 1);
            int cx0 = min(max(x0, 0), WW - 1),   cx1 = min(max(x0 + 1, 0), WW - 1);
            float* wp = s ? wB : wA;
            int*   op = s ? oB : oA;
            wp[0] = (vy0 && vx0) ? wy0 * wx0 * m : 0.f;
            wp[1] = (vy0 && vx1) ? wy0 * wx1 * m : 0.f;
            wp[2] = (vy1 && vx0) ? wy1 * wx0 * m : 0.f;
            wp[3] = (vy1 && vx1) ? wy1 * wx1 * m : 0.f;
            op[0] = cy0 * WW + cx0; op[1] = cy0 * WW + cx1;
            op[2] = cy1 * WW + cx0; op[3] = cy1 * WW + cx1;
        }

        const float2* bph = g_wFh + (tap * 8) * 8 * 32 + lane;
        const float2* bpl = g_wFl + (tap * 8) * 8 * 32 + lane;

        for (int ks = 0; ks < 8; ks++) {
            int c0 = ks * 8 + (lane & 3);
            const float* pc0 = xb + c0 * HWp;
            const float* pc1 = pc0 + 4 * HWp;

            float va0 = wA[0]*pc0[oA[0]] + wA[1]*pc0[oA[1]] + wA[2]*pc0[oA[2]] + wA[3]*pc0[oA[3]];
            float va1 = wB[0]*pc0[oB[0]] + wB[1]*pc0[oB[1]] + wB[2]*pc0[oB[2]] + wB[3]*pc0[oB[3]];
            float va2 = wA[0]*pc1[oA[0]] + wA[1]*pc1[oA[1]] + wA[2]*pc1[oA[2]] + wA[3]*pc1[oA[3]];
            float va3 = wB[0]*pc1[oB[0]] + wB[1]*pc1[oB[1]] + wB[2]*pc1[oB[2]] + wB[3]*pc1[oB[3]];

            uint32_t h0 = cvt_tf32(va0); uint32_t l0 = cvt_tf32(va0 - __uint_as_float(h0));
            uint32_t h1 = cvt_tf32(va1); uint32_t l1 = cvt_tf32(va1 - __uint_as_float(h1));
            uint32_t h2 = cvt_tf32(va2); uint32_t l2 = cvt_tf32(va2 - __uint_as_float(h2));
            uint32_t h3 = cvt_tf32(va3); uint32_t l3 = cvt_tf32(va3 - __uint_as_float(h3));

            const float2* bqh = bph + ks * 8 * 32;
            const float2* bql = bpl + ks * 8 * 32;
#pragma unroll
            for (int nt = 0; nt < 8; nt++) {
                float2 bh = __ldg(bqh + nt * 32);
                float2 bl = __ldg(bql + nt * 32);
                uint32_t bh0 = __float_as_uint(bh.x), bh1 = __float_as_uint(bh.y);
                uint32_t bl0 = __float_as_uint(bl.x), bl1 = __float_as_uint(bl.y);
                mma_t(acc[nt], h0, h1, h2, h3, bh0, bh1);
                mma_t(acc[nt], l0, l1, l2, l3, bh0, bh1);
                mma_t(acc[nt], h0, h1, h2, h3, bl0, bl1);
            }
        }
    }

    float* tb = g_tmp + b * Cout * HWp + y * WW;
#pragma unroll
    for (int nt = 0; nt < 8; nt++) {
        int o = nt * 8 + (lane & 3) * 2;
        tb[o * HWp + p0]       = acc[nt][0];
        tb[(o + 1) * HWp + p0] = acc[nt][1];
        tb[o * HWp + p1]       = acc[nt][2];
        tb[(o + 1) * HWp + p1] = acc[nt][3];
    }
}

// ---------------------------------------------------------------------------
// kC: per-channel mean/var (1024 thr, float4, shuffle reduce)
// ---------------------------------------------------------------------------
__global__ __launch_bounds__(1024) void kC(const float* __restrict__ gamma,
                                           const float* __restrict__ beta)
{
    __shared__ float ss[32], sq[32];
    int c = blockIdx.x, tid = threadIdx.x;
    float s = 0.f, q = 0.f;
#pragma unroll
    for (int b = 0; b < Bsz; b++) {
        const float4* t = (const float4*)(g_tmp + (b * Cout + c) * HWp);
        for (int i = tid; i < HWp / 4; i += 1024) {
            float4 v = t[i];
            s += v.x + v.y + v.z + v.w;
            q += v.x * v.x + v.y * v.y + v.z * v.z + v.w * v.w;
        }
    }
#pragma unroll
    for (int o = 16; o > 0; o >>= 1) {
        s += __shfl_down_sync(0xffffffff, s, o);
        q += __shfl_down_sync(0xffffffff, q, o);
    }
    if ((tid & 31) == 0) { ss[tid >> 5] = s; sq[tid >> 5] = q; }
    __syncthreads();
    if (tid < 32) {
        s = ss[tid]; q = sq[tid];
#pragma unroll
        for (int o = 16; o > 0; o >>= 1) {
            s += __shfl_down_sync(0xffffffff, s, o);
            q += __shfl_down_sync(0xffffffff, q, o);
        }
        if (tid == 0) {
            float n = (float)(Bsz * HWp);
            float mean = s / n;
            float var  = q / n - mean * mean;
            float sc = gamma[c] * rsqrtf(var + 1e-5f);
            g_bn[c] = sc;
            g_bn[Cout + c] = beta[c] - mean * sc;
        }
    }
}

// ---------------------------------------------------------------------------
// kD: elementwise BN affine + ReLU (float4)
// ---------------------------------------------------------------------------
__global__ void kD(float* __restrict__ out)
{
    int i = blockIdx.x * 256 + threadIdx.x;
    const float4* t4 = (const float4*)g_tmp;
    float4 v = t4[i];
    int c = (i >> 12) & 63;
    float sc = g_bn[c], sh = g_bn[Cout + c];
    float4 r;
    r.x = fmaxf(v.x * sc + sh, 0.f);
    r.y = fmaxf(v.y * sc + sh, 0.f);
    r.z = fmaxf(v.z * sc + sh, 0.f);
    r.w = fmaxf(v.w * sc + sh, 0.f);
    ((float4*)out)[i] = r;
}

// ---------------------------------------------------------------------------
extern "C" void kernel_launch(void* const* d_in, const int* in_sizes, int n_in,
                              void* d_out, int out_size)
{
    const float* x      = (const float*)d_in[0];
    const float* conv_w = (const float*)d_in[1];
    const float* off_w  = (const float*)d_in[2];
    const float* off_b  = (const float*)d_in[3];
    const float* mask_w = (const float*)d_in[4];
    const float* mask_b = (const float*)d_in[5];
    const float* gamma  = (const float*)d_in[6];
    const float* beta   = (const float*)d_in[7];
    float* out = (float*)d_out;

    kWB<<<72, 256>>>(conv_w);
    kWA<<<36, 256>>>(off_w, mask_w);
    kA3<<<256, 256>>>(x, off_b, mask_b);
    kB3<<<256, 256>>>(x);
    kC<<<Cout, 1024>>>(gamma, beta);
    kD<<<(Bsz * Cout * HWp / 4) / 256, 256>>>(out);
}

// round 4
// speedup vs baseline: 1.2834x; 1.0665x over previous
#include <cuda_runtime.h>
#include <cstdint>
#include <math.h>

#define HH 128
#define WW 128
#define HWp 16384
#define Cin 64
#define Cout 64
#define Bsz 2
#define NPIX 32768

// ---------------------------------------------------------------------------
// Scratch (no allocations allowed)
// ---------------------------------------------------------------------------
__device__ float  g_om[Bsz*27*HWp];     // 18 raw offsets + 9 sigmoided masks
__device__ float4 g_wF4[9*8*8*32];      // kB B-frags packed: (hi0,hi1,lo0,lo1) [tap][ks][nt][lane]
__device__ float2 g_wAF[9*8*4*32];      // kA B-frags: [tap][ks][nt4][lane]
__device__ float  g_tmp[Bsz*Cout*HWp];  // pre-BN conv output (NCHW)
__device__ float  g_bn[2*Cout];         // scale, shift

// ---------------------------------------------------------------------------
__device__ __forceinline__ uint32_t cvt_tf32(float v) {
    uint32_t r;
    asm("cvt.rna.tf32.f32 %0, %1;" : "=r"(r) : "f"(v));
    return r;
}
__device__ __forceinline__ void mma_t(float* d,
    uint32_t a0, uint32_t a1, uint32_t a2, uint32_t a3,
    uint32_t b0, uint32_t b1)
{
    asm volatile("mma.sync.aligned.m16n8k8.row.col.f32.tf32.tf32.f32 "
        "{%0,%1,%2,%3}, {%4,%5,%6,%7}, {%8,%9}, {%0,%1,%2,%3};"
        : "+f"(d[0]), "+f"(d[1]), "+f"(d[2]), "+f"(d[3])
        : "r"(a0), "r"(a1), "r"(a2), "r"(a3), "r"(b0), "r"(b1));
}

// ---------------------------------------------------------------------------
// kWB: pack conv_w into mma B-fragment layout, hi/lo tf32 split in one float4.
// ---------------------------------------------------------------------------
__global__ void kWB(const float* __restrict__ w)
{
    int i = blockIdx.x * 256 + threadIdx.x;        // 9*8*8*32 = 18432
    if (i >= 9*8*8*32) return;
    int lane = i & 31;
    int nt   = (i >> 5) & 7;
    int ks   = (i >> 8) & 7;
    int tap  = i >> 11;
    int o  = nt * 8 + (lane >> 2);
    int c0 = ks * 8 + (lane & 3);
    float v0 = w[o * 576 + c0 * 9 + tap];
    float v1 = w[o * 576 + (c0 + 4) * 9 + tap];
    uint32_t h0 = cvt_tf32(v0); float l0 = v0 - __uint_as_float(h0);
    uint32_t h1 = cvt_tf32(v1); float l1 = v1 - __uint_as_float(h1);
    g_wF4[i] = make_float4(__uint_as_float(h0), __uint_as_float(h1),
                           __uint_as_float(cvt_tf32(l0)), __uint_as_float(cvt_tf32(l1)));
}

// ---------------------------------------------------------------------------
// kWA: pack offset(18)+mask(9) conv weights (padded to n=32) into B-fragments.
// ---------------------------------------------------------------------------
__global__ void kWA(const float* __restrict__ off_w, const float* __restrict__ mask_w)
{
    int i = blockIdx.x * 256 + threadIdx.x;        // 9*8*4*32 = 9216
    if (i >= 9*8*4*32) return;
    int lane = i & 31;
    int nt   = (i >> 5) & 3;
    int ks   = (i >> 7) & 7;
    int tap  = i >> 10;
    int o  = nt * 8 + (lane >> 2);
    int c0 = ks * 8 + (lane & 3);
    float v0 = 0.f, v1 = 0.f;
    if (o < 18) {
        v0 = off_w[o * 576 + c0 * 9 + tap];
        v1 = off_w[o * 576 + (c0 + 4) * 9 + tap];
    } else if (o < 27) {
        v0 = mask_w[(o - 18) * 576 + c0 * 9 + tap];
        v1 = mask_w[(o - 18) * 576 + (c0 + 4) * 9 + tap];
    }
    g_wAF[i] = make_float2(__uint_as_float(cvt_tf32(v0)), __uint_as_float(cvt_tf32(v1)));
}

// ---------------------------------------------------------------------------
// kA3: offset/mask conv as tensor-core GEMM (K=576, N=27 pad 32), 1 tf32 part.
// ---------------------------------------------------------------------------
__global__ __launch_bounds__(256) void kA3(
    const float* __restrict__ x,
    const float* __restrict__ off_b, const float* __restrict__ mask_b)
{
    int tid = threadIdx.x, wid = tid >> 5, lane = tid & 31;
    int b = blockIdx.x >> 7, y = blockIdx.x & 127;
    int p0 = wid * 16 + (lane >> 2), p1 = p0 + 8;
    const float* xb = x + b * Cin * HWp;

    float acc[4][4];
#pragma unroll
    for (int n = 0; n < 4; n++)
#pragma unroll
        for (int j = 0; j < 4; j++) acc[n][j] = 0.f;

    for (int tap = 0; tap < 9; tap++) {
        int dy = tap / 3 - 1, dx = tap % 3 - 1;
        int yy = y + dy;
        bool vy = ((unsigned)yy < HH);
        int yc = vy ? yy : 0;
        int px0 = p0 + dx, px1 = p1 + dx;
        bool v0 = vy && ((unsigned)px0 < WW);
        bool v1 = vy && ((unsigned)px1 < WW);
        int q0 = v0 ? px0 : 0, q1 = v1 ? px1 : 0;
        const float* xr = xb + yc * WW;
        const float2* bp = g_wAF + (tap * 8) * 4 * 32 + lane;

        for (int ks = 0; ks < 8; ks++) {
            int c0 = ks * 8 + (lane & 3);
            const float* pc0 = xr + c0 * HWp;
            const float* pc1 = pc0 + 4 * HWp;
            uint32_t a0 = cvt_tf32(v0 ? pc0[q0] : 0.f);
            uint32_t a1 = cvt_tf32(v1 ? pc0[q1] : 0.f);
            uint32_t a2 = cvt_tf32(v0 ? pc1[q0] : 0.f);
            uint32_t a3 = cvt_tf32(v1 ? pc1[q1] : 0.f);
            const float2* bq = bp + ks * 4 * 32;
#pragma unroll
            for (int nt = 0; nt < 4; nt++) {
                float2 bv = __ldg(bq + nt * 32);
                mma_t(acc[nt], a0, a1, a2, a3,
                      __float_as_uint(bv.x), __float_as_uint(bv.y));
            }
        }
    }

    float* omb = g_om + b * 27 * HWp;
    int yx0 = y * WW + p0, yx1 = y * WW + p1;
#pragma unroll
    for (int nt = 0; nt < 4; nt++) {
        int o = nt * 8 + (lane & 3) * 2;
#pragma unroll
        for (int j = 0; j < 2; j++) {
            int oc = o + j;
            if (oc < 27) {
                float bias = (oc < 18) ? off_b[oc] : mask_b[oc - 18];
                float r0 = acc[nt][j] + bias;
                float r1 = acc[nt][j + 2] + bias;
                if (oc >= 18) {
                    r0 = 1.f / (1.f + expf(-r0));
                    r1 = 1.f / (1.f + expf(-r1));
                }
                omb[oc * HWp + yx0] = r0;
                omb[oc * HWp + yx1] = r1;
            }
        }
    }
}

// ---------------------------------------------------------------------------
// kB4: fused deformable gather + mma.sync tf32 GEMM, K-split across warp pairs.
// CTA = 128 thr: 2 pixel-groups (16 px each) x 2 K-halves (32 channels each).
// Grid = 1024 (32 pixels per CTA) -> 4096 warps for latency hiding.
// Partial sums reduced through smem, khalf-0 warps write NCHW output.
// ---------------------------------------------------------------------------
__global__ __launch_bounds__(128, 5) void kB4(const float* __restrict__ x)
{
    __shared__ float red[2][32][33];   // [pg][lane][acc j], padded vs bank conflicts

    int tid = threadIdx.x, wid = tid >> 5, lane = tid & 31;
    int pg = wid & 1, kh = wid >> 1;
    int sidx = blockIdx.x;
    int b = sidx >> 9;
    int y = (sidx >> 2) & 127;
    int p0 = (sidx & 3) * 32 + pg * 16 + (lane >> 2);
    int p1 = p0 + 8;
    const float* xb  = x + b * Cin * HWp;
    const float* omb = g_om + b * 27 * HWp;
    int yx0 = y * WW + p0, yx1 = y * WW + p1;

    float acc[8][4];
#pragma unroll
    for (int n = 0; n < 8; n++)
#pragma unroll
        for (int j = 0; j < 4; j++) acc[n][j] = 0.f;

    for (int tap = 0; tap < 9; tap++) {
        // ---- bilinear setup for both pixels ----
        float wA[4], wB[4];
        int   oA[4], oB[4];
#pragma unroll
        for (int s = 0; s < 2; s++) {
            int yx = s ? yx1 : yx0;
            int px = s ? p1 : p0;
            float ofy = omb[(2 * tap) * HWp + yx];
            float ofx = omb[(2 * tap + 1) * HWp + yx];
            float m   = omb[(18 + tap) * HWp + yx];
            float py = ofy + (float)y  + (float)(tap / 3) - 1.f;
            float pxx = ofx + (float)px + (float)(tap % 3) - 1.f;
            float fy = floorf(py), fx = floorf(pxx);
            int   y0 = (int)fy,    x0 = (int)fx;
            float wy1 = py - fy,  wx1 = pxx - fx;
            float wy0 = 1.f - wy1, wx0 = 1.f - wx1;
            bool vy0 = ((unsigned)y0 < HH),      vy1 = ((unsigned)(y0 + 1) < HH);
            bool vx0 = ((unsigned)x0 < WW),      vx1 = ((unsigned)(x0 + 1) < WW);
            int cy0 = min(max(y0, 0), HH - 1),   cy1 = min(max(y0 + 1, 0), HH - 1);
            int cx0 = min(max(x0, 0), WW - 1),   cx1 = min(max(x0 + 1, 0), WW - 1);
            float* wp = s ? wB : wA;
            int*   op = s ? oB : oA;
            wp[0] = (vy0 && vx0) ? wy0 * wx0 * m : 0.f;
            wp[1] = (vy0 && vx1) ? wy0 * wx1 * m : 0.f;
            wp[2] = (vy1 && vx0) ? wy1 * wx0 * m : 0.f;
            wp[3] = (vy1 && vx1) ? wy1 * wx1 * m : 0.f;
            op[0] = cy0 * WW + cx0; op[1] = cy0 * WW + cx1;
            op[2] = cy1 * WW + cx0; op[3] = cy1 * WW + cx1;
        }

        const float4* bp = g_wF4 + (tap * 8) * 8 * 32 + lane;

#pragma unroll
        for (int kq = 0; kq < 4; kq++) {
            int ks = kh * 4 + kq;
            int c0 = ks * 8 + (lane & 3);
            const float* pc0 = xb + c0 * HWp;
            const float* pc1 = pc0 + 4 * HWp;

            float va0 = wA[0]*pc0[oA[0]] + wA[1]*pc0[oA[1]] + wA[2]*pc0[oA[2]] + wA[3]*pc0[oA[3]];
            float va1 = wB[0]*pc0[oB[0]] + wB[1]*pc0[oB[1]] + wB[2]*pc0[oB[2]] + wB[3]*pc0[oB[3]];
            float va2 = wA[0]*pc1[oA[0]] + wA[1]*pc1[oA[1]] + wA[2]*pc1[oA[2]] + wA[3]*pc1[oA[3]];
            float va3 = wB[0]*pc1[oB[0]] + wB[1]*pc1[oB[1]] + wB[2]*pc1[oB[2]] + wB[3]*pc1[oB[3]];

            uint32_t h0 = cvt_tf32(va0); uint32_t l0 = cvt_tf32(va0 - __uint_as_float(h0));
            uint32_t h1 = cvt_tf32(va1); uint32_t l1 = cvt_tf32(va1 - __uint_as_float(h1));
            uint32_t h2 = cvt_tf32(va2); uint32_t l2 = cvt_tf32(va2 - __uint_as_float(h2));
            uint32_t h3 = cvt_tf32(va3); uint32_t l3 = cvt_tf32(va3 - __uint_as_float(h3));

            const float4* bq = bp + ks * 8 * 32;
#pragma unroll
            for (int nt = 0; nt < 8; nt++) {
                float4 bv = __ldg(bq + nt * 32);
                uint32_t bh0 = __float_as_uint(bv.x), bh1 = __float_as_uint(bv.y);
                uint32_t bl0 = __float_as_uint(bv.z), bl1 = __float_as_uint(bv.w);
                mma_t(acc[nt], h0, h1, h2, h3, bh0, bh1);
                mma_t(acc[nt], l0, l1, l2, l3, bh0, bh1);
                mma_t(acc[nt], h0, h1, h2, h3, bl0, bl1);
            }
        }
    }

    // ---- cross-warp K reduction through smem ----
    if (kh == 1) {
#pragma unroll
        for (int n = 0; n < 8; n++)
#pragma unroll
            for (int j = 0; j < 4; j++)
                red[pg][lane][n * 4 + j] = acc[n][j];
    }
    __syncthreads();
    if (kh == 0) {
        float* tb = g_tmp + b * Cout * HWp + y * WW;
#pragma unroll
        for (int nt = 0; nt < 8; nt++) {
            int o = nt * 8 + (lane & 3) * 2;
            float r0 = acc[nt][0] + red[pg][lane][nt * 4 + 0];
            float r1 = acc[nt][1] + red[pg][lane][nt * 4 + 1];
            float r2 = acc[nt][2] + red[pg][lane][nt * 4 + 2];
            float r3 = acc[nt][3] + red[pg][lane][nt * 4 + 3];
            tb[o * HWp + p0]       = r0;
            tb[(o + 1) * HWp + p0] = r1;
            tb[o * HWp + p1]       = r2;
            tb[(o + 1) * HWp + p1] = r3;
        }
    }
}

// ---------------------------------------------------------------------------
// kC: per-channel mean/var (1024 thr, float4, shuffle reduce)
// ---------------------------------------------------------------------------
__global__ __launch_bounds__(1024) void kC(const float* __restrict__ gamma,
                                           const float* __restrict__ beta)
{
    __shared__ float ss[32], sq[32];
    int c = blockIdx.x, tid = threadIdx.x;
    float s = 0.f, q = 0.f;
#pragma unroll
    for (int b = 0; b < Bsz; b++) {
        const float4* t = (const float4*)(g_tmp + (b * Cout + c) * HWp);
        for (int i = tid; i < HWp / 4; i += 1024) {
            float4 v = t[i];
            s += v.x + v.y + v.z + v.w;
            q += v.x * v.x + v.y * v.y + v.z * v.z + v.w * v.w;
        }
    }
#pragma unroll
    for (int o = 16; o > 0; o >>= 1) {
        s += __shfl_down_sync(0xffffffff, s, o);
        q += __shfl_down_sync(0xffffffff, q, o);
    }
    if ((tid & 31) == 0) { ss[tid >> 5] = s; sq[tid >> 5] = q; }
    __syncthreads();
    if (tid < 32) {
        s = ss[tid]; q = sq[tid];
#pragma unroll
        for (int o = 16; o > 0; o >>= 1) {
            s += __shfl_down_sync(0xffffffff, s, o);
            q += __shfl_down_sync(0xffffffff, q, o);
        }
        if (tid == 0) {
            float n = (float)(Bsz * HWp);
            float mean = s / n;
            float var  = q / n - mean * mean;
            float sc = gamma[c] * rsqrtf(var + 1e-5f);
            g_bn[c] = sc;
            g_bn[Cout + c] = beta[c] - mean * sc;
        }
    }
}

// ---------------------------------------------------------------------------
// kD: elementwise BN affine + ReLU (float4)
// ---------------------------------------------------------------------------
__global__ void kD(float* __restrict__ out)
{
    int i = blockIdx.x * 256 + threadIdx.x;
    const float4* t4 = (const float4*)g_tmp;
    float4 v = t4[i];
    int c = (i >> 12) & 63;
    float sc = g_bn[c], sh = g_bn[Cout + c];
    float4 r;
    r.x = fmaxf(v.x * sc + sh, 0.f);
    r.y = fmaxf(v.y * sc + sh, 0.f);
    r.z = fmaxf(v.z * sc + sh, 0.f);
    r.w = fmaxf(v.w * sc + sh, 0.f);
    ((float4*)out)[i] = r;
}

// ---------------------------------------------------------------------------
extern "C" void kernel_launch(void* const* d_in, const int* in_sizes, int n_in,
                              void* d_out, int out_size)
{
    const float* x      = (const float*)d_in[0];
    const float* conv_w = (const float*)d_in[1];
    const float* off_w  = (const float*)d_in[2];
    const float* off_b  = (const float*)d_in[3];
    const float* mask_w = (const float*)d_in[4];
    const float* mask_b = (const float*)d_in[5];
    const float* gamma  = (const float*)d_in[6];
    const float* beta   = (const float*)d_in[7];
    float* out = (float*)d_out;

    kWB<<<72, 256>>>(conv_w);
    kWA<<<36, 256>>>(off_w, mask_w);
    kA3<<<256, 256>>>(x, off_b, mask_b);
    kB4<<<1024, 128>>>(x);
    kC<<<Cout, 1024>>>(gamma, beta);
    kD<<<(Bsz * Cout * HWp / 4) / 256, 256>>>(out);
}

// round 5
// speedup vs baseline: 1.5315x; 1.1933x over previous
#include <cuda_runtime.h>
#include <cstdint>
#include <math.h>

#define HH 128
#define WW 128
#define HWp 16384
#define Cin 64
#define Cout 64
#define Bsz 2
#define NPIX 32768

// ---------------------------------------------------------------------------
// Scratch (no allocations allowed)
// ---------------------------------------------------------------------------
__device__ float  g_om[Bsz*27*HWp];     // 18 raw offsets + 9 sigmoided masks
__device__ float4 g_wF4[9*8*8*32];      // kB B-frags packed: (hi0,hi1,lo0,lo1) [tap][ks][nt][lane]
__device__ float2 g_wAF[9*8*4*32];      // kA B-frags: [tap][ks][nt4][lane]
__device__ float  g_tmp[Bsz*Cout*HWp];  // pre-BN conv output (NCHW)
__device__ float  g_part[512*2];        // kC partial sums [c*8+slab][{s,q}]
__device__ float  g_bn[2*Cout];         // scale, shift

// ---------------------------------------------------------------------------
__device__ __forceinline__ uint32_t cvt_tf32(float v) {
    uint32_t r;
    asm("cvt.rna.tf32.f32 %0, %1;" : "=r"(r) : "f"(v));
    return r;
}
__device__ __forceinline__ void mma_t(float* d,
    uint32_t a0, uint32_t a1, uint32_t a2, uint32_t a3,
    uint32_t b0, uint32_t b1)
{
    asm volatile("mma.sync.aligned.m16n8k8.row.col.f32.tf32.tf32.f32 "
        "{%0,%1,%2,%3}, {%4,%5,%6,%7}, {%8,%9}, {%0,%1,%2,%3};"
        : "+f"(d[0]), "+f"(d[1]), "+f"(d[2]), "+f"(d[3])
        : "r"(a0), "r"(a1), "r"(a2), "r"(a3), "r"(b0), "r"(b1));
}

// ---------------------------------------------------------------------------
// kWB: pack conv_w into mma B-fragment layout, hi/lo tf32 split in one float4.
// ---------------------------------------------------------------------------
__global__ void kWB(const float* __restrict__ w)
{
    int i = blockIdx.x * 256 + threadIdx.x;        // 9*8*8*32 = 18432
    if (i >= 9*8*8*32) return;
    int lane = i & 31;
    int nt   = (i >> 5) & 7;
    int ks   = (i >> 8) & 7;
    int tap  = i >> 11;
    int o  = nt * 8 + (lane >> 2);
    int c0 = ks * 8 + (lane & 3);
    float v0 = w[o * 576 + c0 * 9 + tap];
    float v1 = w[o * 576 + (c0 + 4) * 9 + tap];
    uint32_t h0 = cvt_tf32(v0); float l0 = v0 - __uint_as_float(h0);
    uint32_t h1 = cvt_tf32(v1); float l1 = v1 - __uint_as_float(h1);
    g_wF4[i] = make_float4(__uint_as_float(h0), __uint_as_float(h1),
                           __uint_as_float(cvt_tf32(l0)), __uint_as_float(cvt_tf32(l1)));
}

// ---------------------------------------------------------------------------
// kWA: pack offset(18)+mask(9) conv weights (padded to n=32) into B-fragments.
// ---------------------------------------------------------------------------
__global__ void kWA(const float* __restrict__ off_w, const float* __restrict__ mask_w)
{
    int i = blockIdx.x * 256 + threadIdx.x;        // 9*8*4*32 = 9216
    if (i >= 9*8*4*32) return;
    int lane = i & 31;
    int nt   = (i >> 5) & 3;
    int ks   = (i >> 7) & 7;
    int tap  = i >> 10;
    int o  = nt * 8 + (lane >> 2);
    int c0 = ks * 8 + (lane & 3);
    float v0 = 0.f, v1 = 0.f;
    if (o < 18) {
        v0 = off_w[o * 576 + c0 * 9 + tap];
        v1 = off_w[o * 576 + (c0 + 4) * 9 + tap];
    } else if (o < 27) {
        v0 = mask_w[(o - 18) * 576 + c0 * 9 + tap];
        v1 = mask_w[(o - 18) * 576 + (c0 + 4) * 9 + tap];
    }
    g_wAF[i] = make_float2(__uint_as_float(cvt_tf32(v0)), __uint_as_float(cvt_tf32(v1)));
}

// ---------------------------------------------------------------------------
// kA5: offset/mask conv as tensor GEMM, K-split x2 across warp pairs.
// CTA 256 thr: 4 pixel-groups (16 px) x 2 K-halves. Grid 512.
// ---------------------------------------------------------------------------
__global__ __launch_bounds__(256) void kA5(
    const float* __restrict__ x,
    const float* __restrict__ off_b, const float* __restrict__ mask_b)
{
    __shared__ float red[4][16][32];   // [pg][j][lane]

    int tid = threadIdx.x, wid = tid >> 5, lane = tid & 31;
    int pg = wid & 3, kh = wid >> 2;
    int sidx = blockIdx.x;
    int b = sidx >> 8;
    int y = (sidx >> 1) & 127;
    int p0 = (sidx & 1) * 64 + pg * 16 + (lane >> 2);
    int p1 = p0 + 8;
    const float* xb = x + b * Cin * HWp;

    float acc[4][4];
#pragma unroll
    for (int n = 0; n < 4; n++)
#pragma unroll
        for (int j = 0; j < 4; j++) acc[n][j] = 0.f;

    for (int tap = 0; tap < 9; tap++) {
        int dy = tap / 3 - 1, dx = tap % 3 - 1;
        int yy = y + dy;
        bool vy = ((unsigned)yy < HH);
        int yc = vy ? yy : 0;
        int px0 = p0 + dx, px1 = p1 + dx;
        bool v0 = vy && ((unsigned)px0 < WW);
        bool v1 = vy && ((unsigned)px1 < WW);
        int q0 = v0 ? px0 : 0, q1 = v1 ? px1 : 0;
        const float* xr = xb + yc * WW;
        const float2* bp = g_wAF + (tap * 8) * 4 * 32 + lane;

#pragma unroll
        for (int kq = 0; kq < 4; kq++) {
            int ks = kh * 4 + kq;
            int c0 = ks * 8 + (lane & 3);
            const float* pc0 = xr + c0 * HWp;
            const float* pc1 = pc0 + 4 * HWp;
            uint32_t a0 = cvt_tf32(v0 ? pc0[q0] : 0.f);
            uint32_t a1 = cvt_tf32(v1 ? pc0[q1] : 0.f);
            uint32_t a2 = cvt_tf32(v0 ? pc1[q0] : 0.f);
            uint32_t a3 = cvt_tf32(v1 ? pc1[q1] : 0.f);
            const float2* bq = bp + ks * 4 * 32;
#pragma unroll
            for (int nt = 0; nt < 4; nt++) {
                float2 bv = __ldg(bq + nt * 32);
                mma_t(acc[nt], a0, a1, a2, a3,
                      __float_as_uint(bv.x), __float_as_uint(bv.y));
            }
        }
    }

    if (kh == 1) {
#pragma unroll
        for (int n = 0; n < 4; n++)
#pragma unroll
            for (int j = 0; j < 4; j++)
                red[pg][n * 4 + j][lane] = acc[n][j];
    }
    __syncthreads();
    if (kh == 0) {
        float* omb = g_om + b * 27 * HWp;
        int yx0 = y * WW + p0, yx1 = y * WW + p1;
#pragma unroll
        for (int nt = 0; nt < 4; nt++) {
            int o = nt * 8 + (lane & 3) * 2;
#pragma unroll
            for (int j = 0; j < 2; j++) {
                int oc = o + j;
                if (oc < 27) {
                    float bias = (oc < 18) ? off_b[oc] : mask_b[oc - 18];
                    float r0 = acc[nt][j]     + red[pg][nt * 4 + j][lane]     + bias;
                    float r1 = acc[nt][j + 2] + red[pg][nt * 4 + j + 2][lane] + bias;
                    if (oc >= 18) {
                        r0 = 1.f / (1.f + expf(-r0));
                        r1 = 1.f / (1.f + expf(-r1));
                    }
                    omb[oc * HWp + yx0] = r0;
                    omb[oc * HWp + yx1] = r1;
                }
            }
        }
    }
}

// ---------------------------------------------------------------------------
// kB5: fused deformable gather + mma.sync tf32 GEMM, K-split x4.
// CTA 128 thr = 4 warps sharing one 16-pixel group; warp kh owns 16 channels.
// Grid 2048 -> 8192 warps. Transposed smem reduction, warp 0 writes NCHW.
// ---------------------------------------------------------------------------
__global__ __launch_bounds__(128, 6) void kB5(const float* __restrict__ x)
{
    __shared__ float red[3][32][32];   // [src warp-1][j][lane]

    int tid = threadIdx.x, kh = tid >> 5, lane = tid & 31;
    int sidx = blockIdx.x;
    int b = sidx >> 10;
    int y = (sidx >> 3) & 127;
    int p0 = (sidx & 7) * 16 + (lane >> 2);
    int p1 = p0 + 8;
    const float* xb  = x + b * Cin * HWp;
    const float* omb = g_om + b * 27 * HWp;
    int yx0 = y * WW + p0, yx1 = y * WW + p1;

    float acc[8][4];
#pragma unroll
    for (int n = 0; n < 8; n++)
#pragma unroll
        for (int j = 0; j < 4; j++) acc[n][j] = 0.f;

    for (int tap = 0; tap < 9; tap++) {
        // ---- bilinear setup for both pixels ----
        float wA[4], wB[4];
        int   oA[4], oB[4];
#pragma unroll
        for (int s = 0; s < 2; s++) {
            int yx = s ? yx1 : yx0;
            int px = s ? p1 : p0;
            float ofy = omb[(2 * tap) * HWp + yx];
            float ofx = omb[(2 * tap + 1) * HWp + yx];
            float m   = omb[(18 + tap) * HWp + yx];
            float py = ofy + (float)y  + (float)(tap / 3) - 1.f;
            float pxx = ofx + (float)px + (float)(tap % 3) - 1.f;
            float fy = floorf(py), fx = floorf(pxx);
            int   y0 = (int)fy,    x0 = (int)fx;
            float wy1 = py - fy,  wx1 = pxx - fx;
            float wy0 = 1.f - wy1, wx0 = 1.f - wx1;
            bool vy0 = ((unsigned)y0 < HH),      vy1 = ((unsigned)(y0 + 1) < HH);
            bool vx0 = ((unsigned)x0 < WW),      vx1 = ((unsigned)(x0 + 1) < WW);
            int cy0 = min(max(y0, 0), HH - 1),   cy1 = min(max(y0 + 1, 0), HH - 1);
            int cx0 = min(max(x0, 0), WW - 1),   cx1 = min(max(x0 + 1, 0), WW - 1);
            float* wp = s ? wB : wA;
            int*   op = s ? oB : oA;
            wp[0] = (vy0 && vx0) ? wy0 * wx0 * m : 0.f;
            wp[1] = (vy0 && vx1) ? wy0 * wx1 * m : 0.f;
            wp[2] = (vy1 && vx0) ? wy1 * wx0 * m : 0.f;
            wp[3] = (vy1 && vx1) ? wy1 * wx1 * m : 0.f;
            op[0] = cy0 * WW + cx0; op[1] = cy0 * WW + cx1;
            op[2] = cy1 * WW + cx0; op[3] = cy1 * WW + cx1;
        }

        const float4* bp = g_wF4 + (tap * 8) * 8 * 32 + lane;

#pragma unroll
        for (int kq = 0; kq < 2; kq++) {
            int ks = kh * 2 + kq;
            int c0 = ks * 8 + (lane & 3);
            const float* pc0 = xb + c0 * HWp;
            const float* pc1 = pc0 + 4 * HWp;

            float va0 = wA[0]*pc0[oA[0]] + wA[1]*pc0[oA[1]] + wA[2]*pc0[oA[2]] + wA[3]*pc0[oA[3]];
            float va1 = wB[0]*pc0[oB[0]] + wB[1]*pc0[oB[1]] + wB[2]*pc0[oB[2]] + wB[3]*pc0[oB[3]];
            float va2 = wA[0]*pc1[oA[0]] + wA[1]*pc1[oA[1]] + wA[2]*pc1[oA[2]] + wA[3]*pc1[oA[3]];
            float va3 = wB[0]*pc1[oB[0]] + wB[1]*pc1[oB[1]] + wB[2]*pc1[oB[2]] + wB[3]*pc1[oB[3]];

            uint32_t h0 = cvt_tf32(va0); uint32_t l0 = cvt_tf32(va0 - __uint_as_float(h0));
            uint32_t h1 = cvt_tf32(va1); uint32_t l1 = cvt_tf32(va1 - __uint_as_float(h1));
            uint32_t h2 = cvt_tf32(va2); uint32_t l2 = cvt_tf32(va2 - __uint_as_float(h2));
            uint32_t h3 = cvt_tf32(va3); uint32_t l3 = cvt_tf32(va3 - __uint_as_float(h3));

            const float4* bq = bp + ks * 8 * 32;
#pragma unroll
            for (int nt = 0; nt < 8; nt++) {
                float4 bv = __ldg(bq + nt * 32);
                uint32_t bh0 = __float_as_uint(bv.x), bh1 = __float_as_uint(bv.y);
                uint32_t bl0 = __float_as_uint(bv.z), bl1 = __float_as_uint(bv.w);
                mma_t(acc[nt], h0, h1, h2, h3, bh0, bh1);
                mma_t(acc[nt], l0, l1, l2, l3, bh0, bh1);
                mma_t(acc[nt], h0, h1, h2, h3, bl0, bl1);
            }
        }
    }

    // ---- cross-warp K reduction (transposed, conflict-free) ----
    if (kh != 0) {
#pragma unroll
        for (int n = 0; n < 8; n++)
#pragma unroll
            for (int j = 0; j < 4; j++)
                red[kh - 1][n * 4 + j][lane] = acc[n][j];
    }
    __syncthreads();
    if (kh == 0) {
        float* tb = g_tmp + b * Cout * HWp + y * WW;
#pragma unroll
        for (int nt = 0; nt < 8; nt++) {
            int o = nt * 8 + (lane & 3) * 2;
            float r0 = acc[nt][0], r1 = acc[nt][1], r2 = acc[nt][2], r3 = acc[nt][3];
#pragma unroll
            for (int w = 0; w < 3; w++) {
                r0 += red[w][nt * 4 + 0][lane];
                r1 += red[w][nt * 4 + 1][lane];
                r2 += red[w][nt * 4 + 2][lane];
                r3 += red[w][nt * 4 + 3][lane];
            }
            tb[o * HWp + p0]       = r0;
            tb[(o + 1) * HWp + p0] = r1;
            tb[o * HWp + p1]       = r2;
            tb[(o + 1) * HWp + p1] = r3;
        }
    }
}

// ---------------------------------------------------------------------------
// kC1: partial per-channel sums (512 blocks: c*8+slab), kC2: finalize
// ---------------------------------------------------------------------------
__global__ __launch_bounds__(256) void kC1()
{
    __shared__ float ss[8], sq[8];
    int blk = blockIdx.x, tid = threadIdx.x;
    int c = blk >> 3, slab = blk & 7;
    float s = 0.f, q = 0.f;
#pragma unroll
    for (int b = 0; b < Bsz; b++) {
        const float4* t = (const float4*)(g_tmp + (b * Cout + c) * HWp + slab * 2048);
#pragma unroll
        for (int i = 0; i < 2; i++) {
            float4 v = t[tid + i * 256];
            s += v.x + v.y + v.z + v.w;
            q += v.x * v.x + v.y * v.y + v.z * v.z + v.w * v.w;
        }
    }
#pragma unroll
    for (int o = 16; o > 0; o >>= 1) {
        s += __shfl_down_sync(0xffffffff, s, o);
        q += __shfl_down_sync(0xffffffff, q, o);
    }
    if ((tid & 31) == 0) { ss[tid >> 5] = s; sq[tid >> 5] = q; }
    __syncthreads();
    if (tid == 0) {
        float st = 0.f, qt = 0.f;
#pragma unroll
        for (int w = 0; w < 8; w++) { st += ss[w]; qt += sq[w]; }
        g_part[blk * 2] = st;
        g_part[blk * 2 + 1] = qt;
    }
}
__global__ void kC2(const float* __restrict__ gamma, const float* __restrict__ beta)
{
    int c = threadIdx.x;
    float s = 0.f, q = 0.f;
#pragma unroll
    for (int slab = 0; slab < 8; slab++) {
        s += g_part[(c * 8 + slab) * 2];
        q += g_part[(c * 8 + slab) * 2 + 1];
    }
    float n = (float)(Bsz * HWp);
    float mean = s / n;
    float var  = q / n - mean * mean;
    float sc = gamma[c] * rsqrtf(var + 1e-5f);
    g_bn[c] = sc;
    g_bn[Cout + c] = beta[c] - mean * sc;
}

// ---------------------------------------------------------------------------
// kD: elementwise BN affine + ReLU (float4)
// ---------------------------------------------------------------------------
__global__ void kD(float* __restrict__ out)
{
    int i = blockIdx.x * 256 + threadIdx.x;
    const float4* t4 = (const float4*)g_tmp;
    float4 v = t4[i];
    int c = (i >> 12) & 63;
    float sc = g_bn[c], sh = g_bn[Cout + c];
    float4 r;
    r.x = fmaxf(v.x * sc + sh, 0.f);
    r.y = fmaxf(v.y * sc + sh, 0.f);
    r.z = fmaxf(v.z * sc + sh, 0.f);
    r.w = fmaxf(v.w * sc + sh, 0.f);
    ((float4*)out)[i] = r;
}

// ---------------------------------------------------------------------------
extern "C" void kernel_launch(void* const* d_in, const int* in_sizes, int n_in,
                              void* d_out, int out_size)
{
    const float* x      = (const float*)d_in[0];
    const float* conv_w = (const float*)d_in[1];
    const float* off_w  = (const float*)d_in[2];
    const float* off_b  = (const float*)d_in[3];
    const float* mask_w = (const float*)d_in[4];
    const float* mask_b = (const float*)d_in[5];
    const float* gamma  = (const float*)d_in[6];
    const float* beta   = (const float*)d_in[7];
    float* out = (float*)d_out;

    kWB<<<72, 256>>>(conv_w);
    kWA<<<36, 256>>>(off_w, mask_w);
    kA5<<<512, 256>>>(x, off_b, mask_b);
    kB5<<<2048, 128>>>(x);
    kC1<<<512, 256>>>();
    kC2<<<1, 64>>>(gamma, beta);
    kD<<<(Bsz * Cout * HWp / 4) / 256, 256>>>(out);
}

// round 6
// speedup vs baseline: 1.6283x; 1.0632x over previous
#include <cuda_runtime.h>
#include <cstdint>
#include <math.h>

#define HH 128
#define WW 128
#define HWp 16384
#define Cin 64
#define Cout 64
#define Bsz 2
#define NPIX 32768

// ---------------------------------------------------------------------------
// Scratch (no allocations allowed)
// ---------------------------------------------------------------------------
__device__ float  g_om[Bsz*27*HWp];     // 18 raw offsets + 9 sigmoided masks
__device__ float2 g_wF2[9*8*8*32];      // kB B-frags (hi only): [tap][ks][nt][lane]
__device__ float2 g_wAF[9*8*4*32];      // kA B-frags: [tap][ks][nt4][lane]
__device__ float  g_tmp[Bsz*Cout*HWp];  // pre-BN conv output (NCHW)
__device__ float  g_part[512*2];        // kC partial sums
__device__ float  g_bn[2*Cout];         // scale, shift

// ---------------------------------------------------------------------------
__device__ __forceinline__ uint32_t cvt_tf32(float v) {
    uint32_t r;
    asm("cvt.rna.tf32.f32 %0, %1;" : "=r"(r) : "f"(v));
    return r;
}
__device__ __forceinline__ void mma_t(float* d,
    uint32_t a0, uint32_t a1, uint32_t a2, uint32_t a3,
    uint32_t b0, uint32_t b1)
{
    asm volatile("mma.sync.aligned.m16n8k8.row.col.f32.tf32.tf32.f32 "
        "{%0,%1,%2,%3}, {%4,%5,%6,%7}, {%8,%9}, {%0,%1,%2,%3};"
        : "+f"(d[0]), "+f"(d[1]), "+f"(d[2]), "+f"(d[3])
        : "r"(a0), "r"(a1), "r"(a2), "r"(a3), "r"(b0), "r"(b1));
}

// ---------------------------------------------------------------------------
// kWB: pack conv_w into mma B-fragment layout (tf32 hi only).
// ---------------------------------------------------------------------------
__global__ void kWB(const float* __restrict__ w)
{
    int i = blockIdx.x * 256 + threadIdx.x;        // 9*8*8*32 = 18432
    if (i >= 9*8*8*32) return;
    int lane = i & 31;
    int nt   = (i >> 5) & 7;
    int ks   = (i >> 8) & 7;
    int tap  = i >> 11;
    int o  = nt * 8 + (lane >> 2);
    int c0 = ks * 8 + (lane & 3);
    float v0 = w[o * 576 + c0 * 9 + tap];
    float v1 = w[o * 576 + (c0 + 4) * 9 + tap];
    g_wF2[i] = make_float2(__uint_as_float(cvt_tf32(v0)), __uint_as_float(cvt_tf32(v1)));
}

// ---------------------------------------------------------------------------
// kWA: pack offset(18)+mask(9) conv weights (padded to n=32) into B-fragments.
// ---------------------------------------------------------------------------
__global__ void kWA(const float* __restrict__ off_w, const float* __restrict__ mask_w)
{
    int i = blockIdx.x * 256 + threadIdx.x;        // 9*8*4*32 = 9216
    if (i >= 9*8*4*32) return;
    int lane = i & 31;
    int nt   = (i >> 5) & 3;
    int ks   = (i >> 7) & 7;
    int tap  = i >> 10;
    int o  = nt * 8 + (lane >> 2);
    int c0 = ks * 8 + (lane & 3);
    float v0 = 0.f, v1 = 0.f;
    if (o < 18) {
        v0 = off_w[o * 576 + c0 * 9 + tap];
        v1 = off_w[o * 576 + (c0 + 4) * 9 + tap];
    } else if (o < 27) {
        v0 = mask_w[(o - 18) * 576 + c0 * 9 + tap];
        v1 = mask_w[(o - 18) * 576 + (c0 + 4) * 9 + tap];
    }
    g_wAF[i] = make_float2(__uint_as_float(cvt_tf32(v0)), __uint_as_float(cvt_tf32(v1)));
}

// ---------------------------------------------------------------------------
// kA5: offset/mask conv as tensor GEMM, K-split x2 across warp pairs.
// ---------------------------------------------------------------------------
__global__ __launch_bounds__(256) void kA5(
    const float* __restrict__ x,
    const float* __restrict__ off_b, const float* __restrict__ mask_b)
{
    __shared__ float red[4][16][32];   // [pg][j][lane]

    int tid = threadIdx.x, wid = tid >> 5, lane = tid & 31;
    int pg = wid & 3, kh = wid >> 2;
    int sidx = blockIdx.x;
    int b = sidx >> 8;
    int y = (sidx >> 1) & 127;
    int p0 = (sidx & 1) * 64 + pg * 16 + (lane >> 2);
    int p1 = p0 + 8;
    const float* xb = x + b * Cin * HWp;

    float acc[4][4];
#pragma unroll
    for (int n = 0; n < 4; n++)
#pragma unroll
        for (int j = 0; j < 4; j++) acc[n][j] = 0.f;

    for (int tap = 0; tap < 9; tap++) {
        int dy = tap / 3 - 1, dx = tap % 3 - 1;
        int yy = y + dy;
        bool vy = ((unsigned)yy < HH);
        int yc = vy ? yy : 0;
        int px0 = p0 + dx, px1 = p1 + dx;
        bool v0 = vy && ((unsigned)px0 < WW);
        bool v1 = vy && ((unsigned)px1 < WW);
        int q0 = v0 ? px0 : 0, q1 = v1 ? px1 : 0;
        const float* xr = xb + yc * WW;
        const float2* bp = g_wAF + (tap * 8) * 4 * 32 + lane;

#pragma unroll
        for (int kq = 0; kq < 4; kq++) {
            int ks = kh * 4 + kq;
            int c0 = ks * 8 + (lane & 3);
            const float* pc0 = xr + c0 * HWp;
            const float* pc1 = pc0 + 4 * HWp;
            uint32_t a0 = cvt_tf32(v0 ? pc0[q0] : 0.f);
            uint32_t a1 = cvt_tf32(v1 ? pc0[q1] : 0.f);
            uint32_t a2 = cvt_tf32(v0 ? pc1[q0] : 0.f);
            uint32_t a3 = cvt_tf32(v1 ? pc1[q1] : 0.f);
            const float2* bq = bp + ks * 4 * 32;
#pragma unroll
            for (int nt = 0; nt < 4; nt++) {
                float2 bv = __ldg(bq + nt * 32);
                mma_t(acc[nt], a0, a1, a2, a3,
                      __float_as_uint(bv.x), __float_as_uint(bv.y));
            }
        }
    }

    if (kh == 1) {
#pragma unroll
        for (int n = 0; n < 4; n++)
#pragma unroll
            for (int j = 0; j < 4; j++)
                red[pg][n * 4 + j][lane] = acc[n][j];
    }
    __syncthreads();
    if (kh == 0) {
        float* omb = g_om + b * 27 * HWp;
        int yx0 = y * WW + p0, yx1 = y * WW + p1;
#pragma unroll
        for (int nt = 0; nt < 4; nt++) {
            int o = nt * 8 + (lane & 3) * 2;
#pragma unroll
            for (int j = 0; j < 2; j++) {
                int oc = o + j;
                if (oc < 27) {
                    float bias = (oc < 18) ? off_b[oc] : mask_b[oc - 18];
                    float r0 = acc[nt][j]     + red[pg][nt * 4 + j][lane]     + bias;
                    float r1 = acc[nt][j + 2] + red[pg][nt * 4 + j + 2][lane] + bias;
                    if (oc >= 18) {
                        r0 = 1.f / (1.f + expf(-r0));
                        r1 = 1.f / (1.f + expf(-r1));
                    }
                    omb[oc * HWp + yx0] = r0;
                    omb[oc * HWp + yx1] = r1;
                }
            }
        }
    }
}

// ---------------------------------------------------------------------------
// kB6: fused deformable gather + mma tf32 GEMM, K-split x4, 2-term split
// (full-precision A via hi+lo, hi-only B). Grid 2048, 7 CTAs/SM target.
// ---------------------------------------------------------------------------
__global__ __launch_bounds__(128, 7) void kB6(const float* __restrict__ x)
{
    __shared__ float red[3][32][32];   // [src warp-1][j][lane]

    int tid = threadIdx.x, kh = tid >> 5, lane = tid & 31;
    int sidx = blockIdx.x;
    int b = sidx >> 10;
    int y = (sidx >> 3) & 127;
    int p0 = (sidx & 7) * 16 + (lane >> 2);
    int p1 = p0 + 8;
    const float* xb  = x + b * Cin * HWp;
    const float* omb = g_om + b * 27 * HWp;
    int yx0 = y * WW + p0, yx1 = y * WW + p1;

    float acc[8][4];
#pragma unroll
    for (int n = 0; n < 8; n++)
#pragma unroll
        for (int j = 0; j < 4; j++) acc[n][j] = 0.f;

    for (int tap = 0; tap < 9; tap++) {
        // ---- bilinear setup for both pixels ----
        float wA[4], wB[4];
        int   oA[4], oB[4];
#pragma unroll
        for (int s = 0; s < 2; s++) {
            int yx = s ? yx1 : yx0;
            int px = s ? p1 : p0;
            float ofy = omb[(2 * tap) * HWp + yx];
            float ofx = omb[(2 * tap + 1) * HWp + yx];
            float m   = omb[(18 + tap) * HWp + yx];
            float py = ofy + (float)y  + (float)(tap / 3) - 1.f;
            float pxx = ofx + (float)px + (float)(tap % 3) - 1.f;
            float fy = floorf(py), fx = floorf(pxx);
            int   y0 = (int)fy,    x0 = (int)fx;
            float wy1 = py - fy,  wx1 = pxx - fx;
            float wy0 = 1.f - wy1, wx0 = 1.f - wx1;
            bool vy0 = ((unsigned)y0 < HH),      vy1 = ((unsigned)(y0 + 1) < HH);
            bool vx0 = ((unsigned)x0 < WW),      vx1 = ((unsigned)(x0 + 1) < WW);
            int cy0 = min(max(y0, 0), HH - 1),   cy1 = min(max(y0 + 1, 0), HH - 1);
            int cx0 = min(max(x0, 0), WW - 1),   cx1 = min(max(x0 + 1, 0), WW - 1);
            float* wp = s ? wB : wA;
            int*   op = s ? oB : oA;
            wp[0] = (vy0 && vx0) ? wy0 * wx0 * m : 0.f;
            wp[1] = (vy0 && vx1) ? wy0 * wx1 * m : 0.f;
            wp[2] = (vy1 && vx0) ? wy1 * wx0 * m : 0.f;
            wp[3] = (vy1 && vx1) ? wy1 * wx1 * m : 0.f;
            op[0] = cy0 * WW + cx0; op[1] = cy0 * WW + cx1;
            op[2] = cy1 * WW + cx0; op[3] = cy1 * WW + cx1;
        }

        const float2* bp = g_wF2 + (tap * 8) * 8 * 32 + lane;

#pragma unroll
        for (int kq = 0; kq < 2; kq++) {
            int ks = kh * 2 + kq;
            int c0 = ks * 8 + (lane & 3);
            const float* pc0 = xb + c0 * HWp;
            const float* pc1 = pc0 + 4 * HWp;

            float va0 = wA[0]*pc0[oA[0]] + wA[1]*pc0[oA[1]] + wA[2]*pc0[oA[2]] + wA[3]*pc0[oA[3]];
            float va1 = wB[0]*pc0[oB[0]] + wB[1]*pc0[oB[1]] + wB[2]*pc0[oB[2]] + wB[3]*pc0[oB[3]];
            float va2 = wA[0]*pc1[oA[0]] + wA[1]*pc1[oA[1]] + wA[2]*pc1[oA[2]] + wA[3]*pc1[oA[3]];
            float va3 = wB[0]*pc1[oB[0]] + wB[1]*pc1[oB[1]] + wB[2]*pc1[oB[2]] + wB[3]*pc1[oB[3]];

            uint32_t h0 = cvt_tf32(va0); uint32_t l0 = cvt_tf32(va0 - __uint_as_float(h0));
            uint32_t h1 = cvt_tf32(va1); uint32_t l1 = cvt_tf32(va1 - __uint_as_float(h1));
            uint32_t h2 = cvt_tf32(va2); uint32_t l2 = cvt_tf32(va2 - __uint_as_float(h2));
            uint32_t h3 = cvt_tf32(va3); uint32_t l3 = cvt_tf32(va3 - __uint_as_float(h3));

            const float2* bq = bp + ks * 8 * 32;
#pragma unroll
            for (int nt = 0; nt < 8; nt++) {
                float2 bv = __ldg(bq + nt * 32);
                uint32_t bh0 = __float_as_uint(bv.x), bh1 = __float_as_uint(bv.y);
                mma_t(acc[nt], h0, h1, h2, h3, bh0, bh1);
                mma_t(acc[nt], l0, l1, l2, l3, bh0, bh1);
            }
        }
    }

    // ---- cross-warp K reduction (transposed, conflict-free) ----
    if (kh != 0) {
#pragma unroll
        for (int n = 0; n < 8; n++)
#pragma unroll
            for (int j = 0; j < 4; j++)
                red[kh - 1][n * 4 + j][lane] = acc[n][j];
    }
    __syncthreads();
    if (kh == 0) {
        float* tb = g_tmp + b * Cout * HWp + y * WW;
#pragma unroll
        for (int nt = 0; nt < 8; nt++) {
            int o = nt * 8 + (lane & 3) * 2;
            float r0 = acc[nt][0], r1 = acc[nt][1], r2 = acc[nt][2], r3 = acc[nt][3];
#pragma unroll
            for (int w = 0; w < 3; w++) {
                r0 += red[w][nt * 4 + 0][lane];
                r1 += red[w][nt * 4 + 1][lane];
                r2 += red[w][nt * 4 + 2][lane];
                r3 += red[w][nt * 4 + 3][lane];
            }
            tb[o * HWp + p0]       = r0;
            tb[(o + 1) * HWp + p0] = r1;
            tb[o * HWp + p1]       = r2;
            tb[(o + 1) * HWp + p1] = r3;
        }
    }
}

// ---------------------------------------------------------------------------
// kC1: partial per-channel sums (512 blocks), kC2: finalize
// ---------------------------------------------------------------------------
__global__ __launch_bounds__(256) void kC1()
{
    __shared__ float ss[8], sq[8];
    int blk = blockIdx.x, tid = threadIdx.x;
    int c = blk >> 3, slab = blk & 7;
    float s = 0.f, q = 0.f;
#pragma unroll
    for (int b = 0; b < Bsz; b++) {
        const float4* t = (const float4*)(g_tmp + (b * Cout + c) * HWp + slab * 2048);
#pragma unroll
        for (int i = 0; i < 2; i++) {
            float4 v = t[tid + i * 256];
            s += v.x + v.y + v.z + v.w;
            q += v.x * v.x + v.y * v.y + v.z * v.z + v.w * v.w;
        }
    }
#pragma unroll
    for (int o = 16; o > 0; o >>= 1) {
        s += __shfl_down_sync(0xffffffff, s, o);
        q += __shfl_down_sync(0xffffffff, q, o);
    }
    if ((tid & 31) == 0) { ss[tid >> 5] = s; sq[tid >> 5] = q; }
    __syncthreads();
    if (tid == 0) {
        float st = 0.f, qt = 0.f;
#pragma unroll
        for (int w = 0; w < 8; w++) { st += ss[w]; qt += sq[w]; }
        g_part[blk * 2] = st;
        g_part[blk * 2 + 1] = qt;
    }
}
__global__ void kC2(const float* __restrict__ gamma, const float* __restrict__ beta)
{
    int c = threadIdx.x;
    float s = 0.f, q = 0.f;
#pragma unroll
    for (int slab = 0; slab < 8; slab++) {
        s += g_part[(c * 8 + slab) * 2];
        q += g_part[(c * 8 + slab) * 2 + 1];
    }
    float n = (float)(Bsz * HWp);
    float mean = s / n;
    float var  = q / n - mean * mean;
    float sc = gamma[c] * rsqrtf(var + 1e-5f);
    g_bn[c] = sc;
    g_bn[Cout + c] = beta[c] - mean * sc;
}

// ---------------------------------------------------------------------------
// kD: elementwise BN affine + ReLU (float4)
// ---------------------------------------------------------------------------
__global__ void kD(float* __restrict__ out)
{
    int i = blockIdx.x * 256 + threadIdx.x;
    const float4* t4 = (const float4*)g_tmp;
    float4 v = t4[i];
    int c = (i >> 12) & 63;
    float sc = g_bn[c], sh = g_bn[Cout + c];
    float4 r;
    r.x = fmaxf(v.x * sc + sh, 0.f);
    r.y = fmaxf(v.y * sc + sh, 0.f);
    r.z = fmaxf(v.z * sc + sh, 0.f);
    r.w = fmaxf(v.w * sc + sh, 0.f);
    ((float4*)out)[i] = r;
}

// ---------------------------------------------------------------------------
extern "C" void kernel_launch(void* const* d_in, const int* in_sizes, int n_in,
                              void* d_out, int out_size)
{
    const float* x      = (const float*)d_in[0];
    const float* conv_w = (const float*)d_in[1];
    const float* off_w  = (const float*)d_in[2];
    const float* off_b  = (const float*)d_in[3];
    const float* mask_w = (const float*)d_in[4];
    const float* mask_b = (const float*)d_in[5];
    const float* gamma  = (const float*)d_in[6];
    const float* beta   = (const float*)d_in[7];
    float* out = (float*)d_out;

    kWB<<<72, 256>>>(conv_w);
    kWA<<<36, 256>>>(off_w, mask_w);
    kA5<<<512, 256>>>(x, off_b, mask_b);
    kB6<<<2048, 128>>>(x);
    kC1<<<512, 256>>>();
    kC2<<<1, 64>>>(gamma, beta);
    kD<<<(Bsz * Cout * HWp / 4) / 256, 256>>>(out);
}

// round 7
// speedup vs baseline: 2.5780x; 1.5833x over previous
#include <cuda_runtime.h>
#include <cstdint>
#include <math.h>

#define HH 128
#define WW 128
#define HWp 16384
#define Cin 64
#define Cout 64
#define Bsz 2
#define NPIX 32768

// ---------------------------------------------------------------------------
// Scratch (no allocations allowed)
// ---------------------------------------------------------------------------
__device__ float  g_om[Bsz*27*HWp];     // 18 raw offsets + 9 sigmoided masks
__device__ float2 g_wF2[9*8*8*32];      // kB B-frags (hi only): [tap][ks][nt][lane]
__device__ float2 g_wAF[9*8*4*32];      // kA B-frags: [tap][ks][nt4][lane]
__device__ float  g_tmp[Bsz*Cout*HWp];  // pre-BN conv output (NCHW)
__device__ float  g_part[512*2];        // kC partial sums
__device__ float  g_bn[2*Cout];         // scale, shift

// ---------------------------------------------------------------------------
__device__ __forceinline__ uint32_t cvt_tf32(float v) {
    uint32_t r;
    asm("cvt.rna.tf32.f32 %0, %1;" : "=r"(r) : "f"(v));
    return r;
}
__device__ __forceinline__ void mma_t(float* d,
    uint32_t a0, uint32_t a1, uint32_t a2, uint32_t a3,
    uint32_t b0, uint32_t b1)
{
    asm volatile("mma.sync.aligned.m16n8k8.row.col.f32.tf32.tf32.f32 "
        "{%0,%1,%2,%3}, {%4,%5,%6,%7}, {%8,%9}, {%0,%1,%2,%3};"
        : "+f"(d[0]), "+f"(d[1]), "+f"(d[2]), "+f"(d[3])
        : "r"(a0), "r"(a1), "r"(a2), "r"(a3), "r"(b0), "r"(b1));
}

// ---------------------------------------------------------------------------
// kWB: pack conv_w into mma B-fragment layout (tf32 hi only).
// ---------------------------------------------------------------------------
__global__ void kWB(const float* __restrict__ w)
{
    int i = blockIdx.x * 256 + threadIdx.x;        // 9*8*8*32 = 18432
    if (i >= 9*8*8*32) return;
    int lane = i & 31;
    int nt   = (i >> 5) & 7;
    int ks   = (i >> 8) & 7;
    int tap  = i >> 11;
    int o  = nt * 8 + (lane >> 2);
    int c0 = ks * 8 + (lane & 3);
    float v0 = w[o * 576 + c0 * 9 + tap];
    float v1 = w[o * 576 + (c0 + 4) * 9 + tap];
    g_wF2[i] = make_float2(__uint_as_float(cvt_tf32(v0)), __uint_as_float(cvt_tf32(v1)));
}

// ---------------------------------------------------------------------------
// kWA: pack offset(18)+mask(9) conv weights (padded to n=32) into B-fragments.
// ---------------------------------------------------------------------------
__global__ void kWA(const float* __restrict__ off_w, const float* __restrict__ mask_w)
{
    int i = blockIdx.x * 256 + threadIdx.x;        // 9*8*4*32 = 9216
    if (i >= 9*8*4*32) return;
    int lane = i & 31;
    int nt   = (i >> 5) & 3;
    int ks   = (i >> 7) & 7;
    int tap  = i >> 10;
    int o  = nt * 8 + (lane >> 2);
    int c0 = ks * 8 + (lane & 3);
    float v0 = 0.f, v1 = 0.f;
    if (o < 18) {
        v0 = off_w[o * 576 + c0 * 9 + tap];
        v1 = off_w[o * 576 + (c0 + 4) * 9 + tap];
    } else if (o < 27) {
        v0 = mask_w[(o - 18) * 576 + c0 * 9 + tap];
        v1 = mask_w[(o - 18) * 576 + (c0 + 4) * 9 + tap];
    }
    g_wAF[i] = make_float2(__uint_as_float(cvt_tf32(v0)), __uint_as_float(cvt_tf32(v1)));
}

// ---------------------------------------------------------------------------
// kA5: offset/mask conv as tensor GEMM, K-split x2 across warp pairs.
// ---------------------------------------------------------------------------
__global__ __launch_bounds__(256) void kA5(
    const float* __restrict__ x,
    const float* __restrict__ off_b, const float* __restrict__ mask_b)
{
    __shared__ float red[4][16][32];   // [pg][j][lane]

    int tid = threadIdx.x, wid = tid >> 5, lane = tid & 31;
    int pg = wid & 3, kh = wid >> 2;
    int sidx = blockIdx.x;
    int b = sidx >> 8;
    int y = (sidx >> 1) & 127;
    int p0 = (sidx & 1) * 64 + pg * 16 + (lane >> 2);
    int p1 = p0 + 8;
    const float* xb = x + b * Cin * HWp;

    float acc[4][4];
#pragma unroll
    for (int n = 0; n < 4; n++)
#pragma unroll
        for (int j = 0; j < 4; j++) acc[n][j] = 0.f;

    for (int tap = 0; tap < 9; tap++) {
        int dy = tap / 3 - 1, dx = tap % 3 - 1;
        int yy = y + dy;
        bool vy = ((unsigned)yy < HH);
        int yc = vy ? yy : 0;
        int px0 = p0 + dx, px1 = p1 + dx;
        bool v0 = vy && ((unsigned)px0 < WW);
        bool v1 = vy && ((unsigned)px1 < WW);
        int q0 = v0 ? px0 : 0, q1 = v1 ? px1 : 0;
        const float* xr = xb + yc * WW;
        const float2* bp = g_wAF + (tap * 8) * 4 * 32 + lane;

#pragma unroll
        for (int kq = 0; kq < 4; kq++) {
            int ks = kh * 4 + kq;
            int c0 = ks * 8 + (lane & 3);
            const float* pc0 = xr + c0 * HWp;
            const float* pc1 = pc0 + 4 * HWp;
            uint32_t a0 = cvt_tf32(v0 ? pc0[q0] : 0.f);
            uint32_t a1 = cvt_tf32(v1 ? pc0[q1] : 0.f);
            uint32_t a2 = cvt_tf32(v0 ? pc1[q0] : 0.f);
            uint32_t a3 = cvt_tf32(v1 ? pc1[q1] : 0.f);
            const float2* bq = bp + ks * 4 * 32;
#pragma unroll
            for (int nt = 0; nt < 4; nt++) {
                float2 bv = __ldg(bq + nt * 32);
                mma_t(acc[nt], a0, a1, a2, a3,
                      __float_as_uint(bv.x), __float_as_uint(bv.y));
            }
        }
    }

    if (kh == 1) {
#pragma unroll
        for (int n = 0; n < 4; n++)
#pragma unroll
            for (int j = 0; j < 4; j++)
                red[pg][n * 4 + j][lane] = acc[n][j];
    }
    __syncthreads();
    if (kh == 0) {
        float* omb = g_om + b * 27 * HWp;
        int yx0 = y * WW + p0, yx1 = y * WW + p1;
#pragma unroll
        for (int nt = 0; nt < 4; nt++) {
            int o = nt * 8 + (lane & 3) * 2;
#pragma unroll
            for (int j = 0; j < 2; j++) {
                int oc = o + j;
                if (oc < 27) {
                    float bias = (oc < 18) ? off_b[oc] : mask_b[oc - 18];
                    float r0 = acc[nt][j]     + red[pg][nt * 4 + j][lane]     + bias;
                    float r1 = acc[nt][j + 2] + red[pg][nt * 4 + j + 2][lane] + bias;
                    if (oc >= 18) {
                        r0 = 1.f / (1.f + expf(-r0));
                        r1 = 1.f / (1.f + expf(-r1));
                    }
                    omb[oc * HWp + yx0] = r0;
                    omb[oc * HWp + yx1] = r1;
                }
            }
        }
    }
}

// ---------------------------------------------------------------------------
// kB7: fused deformable gather + mma tf32 GEMM, K-split x4, smem-staged tile.
// Per CTA (16 px group): stage x window [64 ch][5 rows][20 cols] in smem once;
// all 9 taps gather via LDS (off the L1TEX wavefront path). Per-tap warp-
// uniform vote falls back to global gather when any offset leaves the window.
// Reduction buffer reuses the tile smem after a sync.
// ---------------------------------------------------------------------------
#define TPLANE 104   // padded 5*20=100 -> 104 words for bank spread

__global__ __launch_bounds__(128, 6) void kB7(const float* __restrict__ x)
{
    __shared__ float ts[64 * TPLANE];   // 26624 B; reused as reduction buffer

    int tid = threadIdx.x, kh = tid >> 5, lane = tid & 31;
    int sidx = blockIdx.x;
    int b = sidx >> 10;
    int y = (sidx >> 3) & 127;
    int p0c = (sidx & 7) * 16;
    int p0 = p0c + (lane >> 2);
    int p1 = p0 + 8;
    const float* xb  = x + b * Cin * HWp;
    const float* omb = g_om + b * 27 * HWp;
    int yx0 = y * WW + p0, yx1 = y * WW + p1;

    // ---- stage tile: rows y-2..y+2, cols p0c-2..p0c+17, all 64 channels ----
    for (int i = tid; i < 64 * 100; i += 128) {
        int c = i / 100;
        int rr = i - c * 100;
        int r = rr / 20, col = rr - r * 20;
        int gy = y - 2 + r, gx = p0c - 2 + col;
        float v = ((unsigned)gy < HH && (unsigned)gx < WW) ? xb[c * HWp + gy * WW + gx] : 0.f;
        ts[c * TPLANE + rr] = v;
    }
    __syncthreads();

    float acc[8][4];
#pragma unroll
    for (int n = 0; n < 8; n++)
#pragma unroll
        for (int j = 0; j < 4; j++) acc[n][j] = 0.f;

    for (int tap = 0; tap < 9; tap++) {
        // ---- bilinear setup for both pixels ----
        float wA[4], wB[4];
        int   oA[4], oB[4];
        int   sA = 0, sB = 0;
        bool  iwA = false, iwB = false;
#pragma unroll
        for (int s = 0; s < 2; s++) {
            int yx = s ? yx1 : yx0;
            int px = s ? p1 : p0;
            float ofy = omb[(2 * tap) * HWp + yx];
            float ofx = omb[(2 * tap + 1) * HWp + yx];
            float m   = omb[(18 + tap) * HWp + yx];
            float py = ofy + (float)y  + (float)(tap / 3) - 1.f;
            float pxx = ofx + (float)px + (float)(tap % 3) - 1.f;
            float fy = floorf(py), fx = floorf(pxx);
            int   y0 = (int)fy,    x0 = (int)fx;
            float wy1 = py - fy,  wx1 = pxx - fx;
            float wy0 = 1.f - wy1, wx0 = 1.f - wx1;
            bool vy0 = ((unsigned)y0 < HH),      vy1 = ((unsigned)(y0 + 1) < HH);
            bool vx0 = ((unsigned)x0 < WW),      vx1 = ((unsigned)(x0 + 1) < WW);
            int cy0 = min(max(y0, 0), HH - 1),   cy1 = min(max(y0 + 1, 0), HH - 1);
            int cx0 = min(max(x0, 0), WW - 1),   cx1 = min(max(x0 + 1, 0), WW - 1);
            float* wp = s ? wB : wA;
            int*   op = s ? oB : oA;
            wp[0] = (vy0 && vx0) ? wy0 * wx0 * m : 0.f;
            wp[1] = (vy0 && vx1) ? wy0 * wx1 * m : 0.f;
            wp[2] = (vy1 && vx0) ? wy1 * wx0 * m : 0.f;
            wp[3] = (vy1 && vx1) ? wy1 * wx1 * m : 0.f;
            op[0] = cy0 * WW + cx0; op[1] = cy0 * WW + cx1;
            op[2] = cy1 * WW + cx0; op[3] = cy1 * WW + cx1;
            // window-relative coords for smem path
            int ry = y0 - y + 2;
            int rx = x0 - p0c + 2;
            bool iw = ((unsigned)ry <= 3u) && ((unsigned)rx <= 18u);
            if (s) { sB = ry * 20 + rx; iwB = iw; }
            else   { sA = ry * 20 + rx; iwA = iw; }
        }

        bool allin = __all_sync(0xffffffffu, iwA && iwB);
        const float2* bp = g_wF2 + (tap * 8) * 8 * 32 + lane;

        if (allin) {
            // ---- smem gather path ----
#pragma unroll
            for (int kq = 0; kq < 2; kq++) {
                int ks = kh * 2 + kq;
                int c0 = ks * 8 + (lane & 3);
                const float* t0 = ts + c0 * TPLANE;
                const float* t1 = t0 + 4 * TPLANE;

                float va0 = wA[0]*t0[sA] + wA[1]*t0[sA+1] + wA[2]*t0[sA+20] + wA[3]*t0[sA+21];
                float va1 = wB[0]*t0[sB] + wB[1]*t0[sB+1] + wB[2]*t0[sB+20] + wB[3]*t0[sB+21];
                float va2 = wA[0]*t1[sA] + wA[1]*t1[sA+1] + wA[2]*t1[sA+20] + wA[3]*t1[sA+21];
                float va3 = wB[0]*t1[sB] + wB[1]*t1[sB+1] + wB[2]*t1[sB+20] + wB[3]*t1[sB+21];

                uint32_t h0 = cvt_tf32(va0); uint32_t l0 = cvt_tf32(va0 - __uint_as_float(h0));
                uint32_t h1 = cvt_tf32(va1); uint32_t l1 = cvt_tf32(va1 - __uint_as_float(h1));
                uint32_t h2 = cvt_tf32(va2); uint32_t l2 = cvt_tf32(va2 - __uint_as_float(h2));
                uint32_t h3 = cvt_tf32(va3); uint32_t l3 = cvt_tf32(va3 - __uint_as_float(h3));

                const float2* bq = bp + ks * 8 * 32;
#pragma unroll
                for (int nt = 0; nt < 8; nt++) {
                    float2 bv = __ldg(bq + nt * 32);
                    uint32_t bh0 = __float_as_uint(bv.x), bh1 = __float_as_uint(bv.y);
                    mma_t(acc[nt], h0, h1, h2, h3, bh0, bh1);
                    mma_t(acc[nt], l0, l1, l2, l3, bh0, bh1);
                }
            }
        } else {
            // ---- fallback: global gather (rare: offsets outside window) ----
#pragma unroll
            for (int kq = 0; kq < 2; kq++) {
                int ks = kh * 2 + kq;
                int c0 = ks * 8 + (lane & 3);
                const float* pc0 = xb + c0 * HWp;
                const float* pc1 = pc0 + 4 * HWp;

                float va0 = wA[0]*pc0[oA[0]] + wA[1]*pc0[oA[1]] + wA[2]*pc0[oA[2]] + wA[3]*pc0[oA[3]];
                float va1 = wB[0]*pc0[oB[0]] + wB[1]*pc0[oB[1]] + wB[2]*pc0[oB[2]] + wB[3]*pc0[oB[3]];
                float va2 = wA[0]*pc1[oA[0]] + wA[1]*pc1[oA[1]] + wA[2]*pc1[oA[2]] + wA[3]*pc1[oA[3]];
                float va3 = wB[0]*pc1[oB[0]] + wB[1]*pc1[oB[1]] + wB[2]*pc1[oB[2]] + wB[3]*pc1[oB[3]];

                uint32_t h0 = cvt_tf32(va0); uint32_t l0 = cvt_tf32(va0 - __uint_as_float(h0));
                uint32_t h1 = cvt_tf32(va1); uint32_t l1 = cvt_tf32(va1 - __uint_as_float(h1));
                uint32_t h2 = cvt_tf32(va2); uint32_t l2 = cvt_tf32(va2 - __uint_as_float(h2));
                uint32_t h3 = cvt_tf32(va3); uint32_t l3 = cvt_tf32(va3 - __uint_as_float(h3));

                const float2* bq = bp + ks * 8 * 32;
#pragma unroll
                for (int nt = 0; nt < 8; nt++) {
                    float2 bv = __ldg(bq + nt * 32);
                    uint32_t bh0 = __float_as_uint(bv.x), bh1 = __float_as_uint(bv.y);
                    mma_t(acc[nt], h0, h1, h2, h3, bh0, bh1);
                    mma_t(acc[nt], l0, l1, l2, l3, bh0, bh1);
                }
            }
        }
    }

    // ---- cross-warp K reduction (reuse tile smem; conflict-free) ----
    __syncthreads();                 // done reading tile
    float* red = ts;                 // [w][j][lane] = ts[w*1024 + j*32 + lane]
    if (kh != 0) {
#pragma unroll
        for (int n = 0; n < 8; n++)
#pragma unroll
            for (int j = 0; j < 4; j++)
                red[(kh - 1) * 1024 + (n * 4 + j) * 32 + lane] = acc[n][j];
    }
    __syncthreads();
    if (kh == 0) {
        float* tb = g_tmp + b * Cout * HWp + y * WW;
#pragma unroll
        for (int nt = 0; nt < 8; nt++) {
            int o = nt * 8 + (lane & 3) * 2;
            float r0 = acc[nt][0], r1 = acc[nt][1], r2 = acc[nt][2], r3 = acc[nt][3];
#pragma unroll
            for (int w = 0; w < 3; w++) {
                r0 += red[w * 1024 + (nt * 4 + 0) * 32 + lane];
                r1 += red[w * 1024 + (nt * 4 + 1) * 32 + lane];
                r2 += red[w * 1024 + (nt * 4 + 2) * 32 + lane];
                r3 += red[w * 1024 + (nt * 4 + 3) * 32 + lane];
            }
            tb[o * HWp + p0]       = r0;
            tb[(o + 1) * HWp + p0] = r1;
            tb[o * HWp + p1]       = r2;
            tb[(o + 1) * HWp + p1] = r3;
        }
    }
}

// ---------------------------------------------------------------------------
// kC1: partial per-channel sums (512 blocks), kC2: finalize
// ---------------------------------------------------------------------------
__global__ __launch_bounds__(256) void kC1()
{
    __shared__ float ss[8], sq[8];
    int blk = blockIdx.x, tid = threadIdx.x;
    int c = blk >> 3, slab = blk & 7;
    float s = 0.f, q = 0.f;
#pragma unroll
    for (int b = 0; b < Bsz; b++) {
        const float4* t = (const float4*)(g_tmp + (b * Cout + c) * HWp + slab * 2048);
#pragma unroll
        for (int i = 0; i < 2; i++) {
            float4 v = t[tid + i * 256];
            s += v.x + v.y + v.z + v.w;
            q += v.x * v.x + v.y * v.y + v.z * v.z + v.w * v.w;
        }
    }
#pragma unroll
    for (int o = 16; o > 0; o >>= 1) {
        s += __shfl_down_sync(0xffffffff, s, o);
        q += __shfl_down_sync(0xffffffff, q, o);
    }
    if ((tid & 31) == 0) { ss[tid >> 5] = s; sq[tid >> 5] = q; }
    __syncthreads();
    if (tid == 0) {
        float st = 0.f, qt = 0.f;
#pragma unroll
        for (int w = 0; w < 8; w++) { st += ss[w]; qt += sq[w]; }
        g_part[blk * 2] = st;
        g_part[blk * 2 + 1] = qt;
    }
}
__global__ void kC2(const float* __restrict__ gamma, const float* __restrict__ beta)
{
    int c = threadIdx.x;
    float s = 0.f, q = 0.f;
#pragma unroll
    for (int slab = 0; slab < 8; slab++) {
        s += g_part[(c * 8 + slab) * 2];
        q += g_part[(c * 8 + slab) * 2 + 1];
    }
    float n = (float)(Bsz * HWp);
    float mean = s / n;
    float var  = q / n - mean * mean;
    float sc = gamma[c] * rsqrtf(var + 1e-5f);
    g_bn[c] = sc;
    g_bn[Cout + c] = beta[c] - mean * sc;
}

// ---------------------------------------------------------------------------
// kD: elementwise BN affine + ReLU (float4)
// ---------------------------------------------------------------------------
__global__ void kD(float* __restrict__ out)
{
    int i = blockIdx.x * 256 + threadIdx.x;
    const float4* t4 = (const float4*)g_tmp;
    float4 v = t4[i];
    int c = (i >> 12) & 63;
    float sc = g_bn[c], sh = g_bn[Cout + c];
    float4 r;
    r.x = fmaxf(v.x * sc + sh, 0.f);
    r.y = fmaxf(v.y * sc + sh, 0.f);
    r.z = fmaxf(v.z * sc + sh, 0.f);
    r.w = fmaxf(v.w * sc + sh, 0.f);
    ((float4*)out)[i] = r;
}

// ---------------------------------------------------------------------------
extern "C" void kernel_launch(void* const* d_in, const int* in_sizes, int n_in,
                              void* d_out, int out_size)
{
    const float* x      = (const float*)d_in[0];
    const float* conv_w = (const float*)d_in[1];
    const float* off_w  = (const float*)d_in[2];
    const float* off_b  = (const float*)d_in[3];
    const float* mask_w = (const float*)d_in[4];
    const float* mask_b = (const float*)d_in[5];
    const float* gamma  = (const float*)d_in[6];
    const float* beta   = (const float*)d_in[7];
    float* out = (float*)d_out;

    kWB<<<72, 256>>>(conv_w);
    kWA<<<36, 256>>>(off_w, mask_w);
    kA5<<<512, 256>>>(x, off_b, mask_b);
    kB7<<<2048, 128>>>(x);
    kC1<<<512, 256>>>();
    kC2<<<1, 64>>>(gamma, beta);
    kD<<<(Bsz * Cout * HWp / 4) / 256, 256>>>(out);
}

// round 8
// speedup vs baseline: 2.7087x; 1.0507x over previous
#include <cuda_runtime.h>
#include <cstdint>
#include <math.h>

#define HH 128
#define WW 128
#define HWp 16384
#define Cin 64
#define Cout 64
#define Bsz 2
#define NPIX 32768

// ---------------------------------------------------------------------------
// Scratch (no allocations allowed)
// ---------------------------------------------------------------------------
__device__ float  g_om[Bsz*27*HWp];     // 18 raw offsets + 9 sigmoided masks
__device__ float2 g_wF2[9*8*8*32];      // kB B-frags (hi only): [tap][ks][nt][lane]
__device__ float2 g_wAF[9*8*4*32];      // kA B-frags: [tap][ks][nt4][lane]
__device__ float  g_tmp[Bsz*Cout*HWp];  // pre-BN conv output (NCHW)
__device__ float  g_part[512*2];        // kC partial sums
__device__ float  g_bn[2*Cout];         // scale, shift

// ---------------------------------------------------------------------------
__device__ __forceinline__ uint32_t cvt_tf32(float v) {
    uint32_t r;
    asm("cvt.rna.tf32.f32 %0, %1;" : "=r"(r) : "f"(v));
    return r;
}
__device__ __forceinline__ void mma_t(float* d,
    uint32_t a0, uint32_t a1, uint32_t a2, uint32_t a3,
    uint32_t b0, uint32_t b1)
{
    asm volatile("mma.sync.aligned.m16n8k8.row.col.f32.tf32.tf32.f32 "
        "{%0,%1,%2,%3}, {%4,%5,%6,%7}, {%8,%9}, {%0,%1,%2,%3};"
        : "+f"(d[0]), "+f"(d[1]), "+f"(d[2]), "+f"(d[3])
        : "r"(a0), "r"(a1), "r"(a2), "r"(a3), "r"(b0), "r"(b1));
}

// ---------------------------------------------------------------------------
// kWB: pack conv_w into mma B-fragment layout (tf32 hi only).
// ---------------------------------------------------------------------------
__global__ void kWB(const float* __restrict__ w)
{
    int i = blockIdx.x * 256 + threadIdx.x;        // 9*8*8*32 = 18432
    if (i >= 9*8*8*32) return;
    int lane = i & 31;
    int nt   = (i >> 5) & 7;
    int ks   = (i >> 8) & 7;
    int tap  = i >> 11;
    int o  = nt * 8 + (lane >> 2);
    int c0 = ks * 8 + (lane & 3);
    float v0 = w[o * 576 + c0 * 9 + tap];
    float v1 = w[o * 576 + (c0 + 4) * 9 + tap];
    g_wF2[i] = make_float2(__uint_as_float(cvt_tf32(v0)), __uint_as_float(cvt_tf32(v1)));
}

// ---------------------------------------------------------------------------
// kWA: pack offset(18)+mask(9) conv weights (padded to n=32) into B-fragments.
// ---------------------------------------------------------------------------
__global__ void kWA(const float* __restrict__ off_w, const float* __restrict__ mask_w)
{
    int i = blockIdx.x * 256 + threadIdx.x;        // 9*8*4*32 = 9216
    if (i >= 9*8*4*32) return;
    int lane = i & 31;
    int nt   = (i >> 5) & 3;
    int ks   = (i >> 7) & 7;
    int tap  = i >> 10;
    int o  = nt * 8 + (lane >> 2);
    int c0 = ks * 8 + (lane & 3);
    float v0 = 0.f, v1 = 0.f;
    if (o < 18) {
        v0 = off_w[o * 576 + c0 * 9 + tap];
        v1 = off_w[o * 576 + (c0 + 4) * 9 + tap];
    } else if (o < 27) {
        v0 = mask_w[(o - 18) * 576 + c0 * 9 + tap];
        v1 = mask_w[(o - 18) * 576 + (c0 + 4) * 9 + tap];
    }
    g_wAF[i] = make_float2(__uint_as_float(cvt_tf32(v0)), __uint_as_float(cvt_tf32(v1)));
}

// ---------------------------------------------------------------------------
// kA5: offset/mask conv as tensor GEMM, K-split x2 across warp pairs.
// ---------------------------------------------------------------------------
__global__ __launch_bounds__(256) void kA5(
    const float* __restrict__ x,
    const float* __restrict__ off_b, const float* __restrict__ mask_b)
{
    __shared__ float red[4][16][32];   // [pg][j][lane]

    int tid = threadIdx.x, wid = tid >> 5, lane = tid & 31;
    int pg = wid & 3, kh = wid >> 2;
    int sidx = blockIdx.x;
    int b = sidx >> 8;
    int y = (sidx >> 1) & 127;
    int p0 = (sidx & 1) * 64 + pg * 16 + (lane >> 2);
    int p1 = p0 + 8;
    const float* xb = x + b * Cin * HWp;

    float acc[4][4];
#pragma unroll
    for (int n = 0; n < 4; n++)
#pragma unroll
        for (int j = 0; j < 4; j++) acc[n][j] = 0.f;

    for (int tap = 0; tap < 9; tap++) {
        int dy = tap / 3 - 1, dx = tap % 3 - 1;
        int yy = y + dy;
        bool vy = ((unsigned)yy < HH);
        int yc = vy ? yy : 0;
        int px0 = p0 + dx, px1 = p1 + dx;
        bool v0 = vy && ((unsigned)px0 < WW);
        bool v1 = vy && ((unsigned)px1 < WW);
        int q0 = v0 ? px0 : 0, q1 = v1 ? px1 : 0;
        const float* xr = xb + yc * WW;
        const float2* bp = g_wAF + (tap * 8) * 4 * 32 + lane;

#pragma unroll
        for (int kq = 0; kq < 4; kq++) {
            int ks = kh * 4 + kq;
            int c0 = ks * 8 + (lane & 3);
            const float* pc0 = xr + c0 * HWp;
            const float* pc1 = pc0 + 4 * HWp;
            uint32_t a0 = cvt_tf32(v0 ? pc0[q0] : 0.f);
            uint32_t a1 = cvt_tf32(v1 ? pc0[q1] : 0.f);
            uint32_t a2 = cvt_tf32(v0 ? pc1[q0] : 0.f);
            uint32_t a3 = cvt_tf32(v1 ? pc1[q1] : 0.f);
            const float2* bq = bp + ks * 4 * 32;
#pragma unroll
            for (int nt = 0; nt < 4; nt++) {
                float2 bv = __ldg(bq + nt * 32);
                mma_t(acc[nt], a0, a1, a2, a3,
                      __float_as_uint(bv.x), __float_as_uint(bv.y));
            }
        }
    }

    if (kh == 1) {
#pragma unroll
        for (int n = 0; n < 4; n++)
#pragma unroll
            for (int j = 0; j < 4; j++)
                red[pg][n * 4 + j][lane] = acc[n][j];
    }
    __syncthreads();
    if (kh == 0) {
        float* omb = g_om + b * 27 * HWp;
        int yx0 = y * WW + p0, yx1 = y * WW + p1;
#pragma unroll
        for (int nt = 0; nt < 4; nt++) {
            int o = nt * 8 + (lane & 3) * 2;
#pragma unroll
            for (int j = 0; j < 2; j++) {
                int oc = o + j;
                if (oc < 27) {
                    float bias = (oc < 18) ? off_b[oc] : mask_b[oc - 18];
                    float r0 = acc[nt][j]     + red[pg][nt * 4 + j][lane]     + bias;
                    float r1 = acc[nt][j + 2] + red[pg][nt * 4 + j + 2][lane] + bias;
                    if (oc >= 18) {
                        r0 = 1.f / (1.f + expf(-r0));
                        r1 = 1.f / (1.f + expf(-r1));
                    }
                    omb[oc * HWp + yx0] = r0;
                    omb[oc * HWp + yx1] = r1;
                }
            }
        }
    }
}

// ---------------------------------------------------------------------------
// kB8: fused deformable gather + mma tf32 GEMM, K-split x4.
// Tile is position-major with channel pairs (c, c+4) adjacent -> LDS.64
// corner loads (half the shared-load count). Bilinear setup computed once
// per CTA into a smem table shared by all 4 K-split warps.
// ---------------------------------------------------------------------------
#define TP 72     // words per tile position (64 ch-words + 8 pad; bank step 8)

__global__ __launch_bounds__(128, 6) void kB8(const float* __restrict__ x)
{
    __shared__ float  ts[100 * TP];     // 28800 B tile; reused as reduction buf
    __shared__ float4 sw[9][16];        // bilinear weights (mask-premultiplied)
    __shared__ int    sp[9][16];        // window pos as word offset (pos*TP)
    __shared__ int    allin[9];

    int tid = threadIdx.x, kh = tid >> 5, lane = tid & 31;
    int sidx = blockIdx.x;
    int b = sidx >> 10;
    int y = (sidx >> 3) & 127;
    int p0c = (sidx & 7) * 16;
    int p0 = p0c + (lane >> 2);
    int p1 = p0 + 8;
    const float* xb  = x + b * Cin * HWp;
    const float* omb = g_om + b * 27 * HWp;
    int yx0 = y * WW + p0, yx1 = y * WW + p1;

    if (tid < 9) allin[tid] = 1;
    __syncthreads();

    // ---- stage tile: rows y-2..y+2, cols p0c-2..p0c+17, channel-pair layout ----
    for (int i = tid; i < 64 * 100; i += 128) {
        int c = i / 100;
        int rr = i - c * 100;
        int r = rr / 20, col = rr - r * 20;
        int gy = y - 2 + r, gx = p0c - 2 + col;
        float v = ((unsigned)gy < HH && (unsigned)gx < WW) ? xb[c * HWp + gy * WW + gx] : 0.f;
        int cw = ((c >> 3) << 3) + ((c & 3) << 1) + ((c >> 2) & 1);
        ts[rr * TP + cw] = v;
    }

    // ---- setup table: 144 (tap, px) items ----
    for (int i = tid; i < 144; i += 128) {
        int tap = i >> 4, px = i & 15;
        int p = p0c + px;
        int yx = y * WW + p;
        float ofy = omb[(2 * tap) * HWp + yx];
        float ofx = omb[(2 * tap + 1) * HWp + yx];
        float m   = omb[(18 + tap) * HWp + yx];
        float py  = ofy + (float)y + (float)(tap / 3) - 1.f;
        float pxx = ofx + (float)p + (float)(tap % 3) - 1.f;
        float fy = floorf(py), fx = floorf(pxx);
        int   y0 = (int)fy,    x0 = (int)fx;
        float wy1 = py - fy,  wx1 = pxx - fx;
        float wy0 = 1.f - wy1, wx0 = 1.f - wx1;
        bool vy0 = ((unsigned)y0 < HH),  vy1 = ((unsigned)(y0 + 1) < HH);
        bool vx0 = ((unsigned)x0 < WW),  vx1 = ((unsigned)(x0 + 1) < WW);
        float4 wv;
        wv.x = (vy0 && vx0) ? wy0 * wx0 * m : 0.f;
        wv.y = (vy0 && vx1) ? wy0 * wx1 * m : 0.f;
        wv.z = (vy1 && vx0) ? wy1 * wx0 * m : 0.f;
        wv.w = (vy1 && vx1) ? wy1 * wx1 * m : 0.f;
        sw[tap][px] = wv;
        int ry = y0 - y + 2;
        int rx = x0 - p0c + 2;
        sp[tap][px] = (ry * 20 + rx) * TP;
        if (!(((unsigned)ry <= 3u) && ((unsigned)rx <= 18u))) allin[tap] = 0;
    }
    __syncthreads();

    float acc[8][4];
#pragma unroll
    for (int n = 0; n < 8; n++)
#pragma unroll
        for (int j = 0; j < 4; j++) acc[n][j] = 0.f;

    for (int tap = 0; tap < 9; tap++) {
        const float2* bp = g_wF2 + (tap * 8) * 8 * 32 + lane;

        if (allin[tap]) {
            // ---- fast path: table + LDS.64 paired-channel gather ----
            float4 wA = sw[tap][lane >> 2];
            float4 wB = sw[tap][8 + (lane >> 2)];
            int baseA = sp[tap][lane >> 2];
            int baseB = sp[tap][8 + (lane >> 2)];
#pragma unroll
            for (int kq = 0; kq < 2; kq++) {
                int ks = kh * 2 + kq;
                int cw = (ks << 3) + ((lane & 3) << 1);
                const float2* tA = (const float2*)(ts + baseA + cw);
                const float2* tB = (const float2*)(ts + baseB + cw);
                float2 A0 = tA[0], A1 = tA[TP/2], A2 = tA[10*TP], A3 = tA[10*TP + TP/2];
                float2 B0 = tB[0], B1 = tB[TP/2], B2 = tB[10*TP], B3 = tB[10*TP + TP/2];

                float va0 = wA.x*A0.x + wA.y*A1.x + wA.z*A2.x + wA.w*A3.x;
                float va1 = wB.x*B0.x + wB.y*B1.x + wB.z*B2.x + wB.w*B3.x;
                float va2 = wA.x*A0.y + wA.y*A1.y + wA.z*A2.y + wA.w*A3.y;
                float va3 = wB.x*B0.y + wB.y*B1.y + wB.z*B2.y + wB.w*B3.y;

                uint32_t h0 = cvt_tf32(va0); uint32_t l0 = cvt_tf32(va0 - __uint_as_float(h0));
                uint32_t h1 = cvt_tf32(va1); uint32_t l1 = cvt_tf32(va1 - __uint_as_float(h1));
                uint32_t h2 = cvt_tf32(va2); uint32_t l2 = cvt_tf32(va2 - __uint_as_float(h2));
                uint32_t h3 = cvt_tf32(va3); uint32_t l3 = cvt_tf32(va3 - __uint_as_float(h3));

                const float2* bq = bp + ks * 8 * 32;
#pragma unroll
                for (int nt = 0; nt < 8; nt++) {
                    float2 bv = __ldg(bq + nt * 32);
                    uint32_t bh0 = __float_as_uint(bv.x), bh1 = __float_as_uint(bv.y);
                    mma_t(acc[nt], h0, h1, h2, h3, bh0, bh1);
                    mma_t(acc[nt], l0, l1, l2, l3, bh0, bh1);
                }
            }
        } else {
            // ---- fallback: exact global gather (rare) ----
            float wA[4], wB[4];
            int   oA[4], oB[4];
#pragma unroll
            for (int s = 0; s < 2; s++) {
                int yx = s ? yx1 : yx0;
                int px = s ? p1 : p0;
                float ofy = omb[(2 * tap) * HWp + yx];
                float ofx = omb[(2 * tap + 1) * HWp + yx];
                float m   = omb[(18 + tap) * HWp + yx];
                float py = ofy + (float)y  + (float)(tap / 3) - 1.f;
                float pxx = ofx + (float)px + (float)(tap % 3) - 1.f;
                float fy = floorf(py), fx = floorf(pxx);
                int   y0 = (int)fy,    x0 = (int)fx;
                float wy1 = py - fy,  wx1 = pxx - fx;
                float wy0 = 1.f - wy1, wx0 = 1.f - wx1;
                bool vy0 = ((unsigned)y0 < HH),      vy1 = ((unsigned)(y0 + 1) < HH);
                bool vx0 = ((unsigned)x0 < WW),      vx1 = ((unsigned)(x0 + 1) < WW);
                int cy0 = min(max(y0, 0), HH - 1),   cy1 = min(max(y0 + 1, 0), HH - 1);
                int cx0 = min(max(x0, 0), WW - 1),   cx1 = min(max(x0 + 1, 0), WW - 1);
                float* wp = s ? wB : wA;
                int*   op = s ? oB : oA;
                wp[0] = (vy0 && vx0) ? wy0 * wx0 * m : 0.f;
                wp[1] = (vy0 && vx1) ? wy0 * wx1 * m : 0.f;
                wp[2] = (vy1 && vx0) ? wy1 * wx0 * m : 0.f;
                wp[3] = (vy1 && vx1) ? wy1 * wx1 * m : 0.f;
                op[0] = cy0 * WW + cx0; op[1] = cy0 * WW + cx1;
                op[2] = cy1 * WW + cx0; op[3] = cy1 * WW + cx1;
            }
#pragma unroll
            for (int kq = 0; kq < 2; kq++) {
                int ks = kh * 2 + kq;
                int c0 = ks * 8 + (lane & 3);
                const float* pc0 = xb + c0 * HWp;
                const float* pc1 = pc0 + 4 * HWp;

                float va0 = wA[0]*pc0[oA[0]] + wA[1]*pc0[oA[1]] + wA[2]*pc0[oA[2]] + wA[3]*pc0[oA[3]];
                float va1 = wB[0]*pc0[oB[0]] + wB[1]*pc0[oB[1]] + wB[2]*pc0[oB[2]] + wB[3]*pc0[oB[3]];
                float va2 = wA[0]*pc1[oA[0]] + wA[1]*pc1[oA[1]] + wA[2]*pc1[oA[2]] + wA[3]*pc1[oA[3]];
                float va3 = wB[0]*pc1[oB[0]] + wB[1]*pc1[oB[1]] + wB[2]*pc1[oB[2]] + wB[3]*pc1[oB[3]];

                uint32_t h0 = cvt_tf32(va0); uint32_t l0 = cvt_tf32(va0 - __uint_as_float(h0));
                uint32_t h1 = cvt_tf32(va1); uint32_t l1 = cvt_tf32(va1 - __uint_as_float(h1));
                uint32_t h2 = cvt_tf32(va2); uint32_t l2 = cvt_tf32(va2 - __uint_as_float(h2));
                uint32_t h3 = cvt_tf32(va3); uint32_t l3 = cvt_tf32(va3 - __uint_as_float(h3));

                const float2* bq = bp + ks * 8 * 32;
#pragma unroll
                for (int nt = 0; nt < 8; nt++) {
                    float2 bv = __ldg(bq + nt * 32);
                    uint32_t bh0 = __float_as_uint(bv.x), bh1 = __float_as_uint(bv.y);
                    mma_t(acc[nt], h0, h1, h2, h3, bh0, bh1);
                    mma_t(acc[nt], l0, l1, l2, l3, bh0, bh1);
                }
            }
        }
    }

    // ---- cross-warp K reduction (reuse tile smem; conflict-free) ----
    __syncthreads();                 // done reading tile
    float* red = ts;                 // [w][j][lane]
    if (kh != 0) {
#pragma unroll
        for (int n = 0; n < 8; n++)
#pragma unroll
            for (int j = 0; j < 4; j++)
                red[(kh - 1) * 1024 + (n * 4 + j) * 32 + lane] = acc[n][j];
    }
    __syncthreads();
    if (kh == 0) {
        float* tb = g_tmp + b * Cout * HWp + y * WW;
#pragma unroll
        for (int nt = 0; nt < 8; nt++) {
            int o = nt * 8 + (lane & 3) * 2;
            float r0 = acc[nt][0], r1 = acc[nt][1], r2 = acc[nt][2], r3 = acc[nt][3];
#pragma unroll
            for (int w = 0; w < 3; w++) {
                r0 += red[w * 1024 + (nt * 4 + 0) * 32 + lane];
                r1 += red[w * 1024 + (nt * 4 + 1) * 32 + lane];
                r2 += red[w * 1024 + (nt * 4 + 2) * 32 + lane];
                r3 += red[w * 1024 + (nt * 4 + 3) * 32 + lane];
            }
            tb[o * HWp + p0]       = r0;
            tb[(o + 1) * HWp + p0] = r1;
            tb[o * HWp + p1]       = r2;
            tb[(o + 1) * HWp + p1] = r3;
        }
    }
}

// ---------------------------------------------------------------------------
// kC1: partial per-channel sums (512 blocks), kC2: finalize
// ---------------------------------------------------------------------------
__global__ __launch_bounds__(256) void kC1()
{
    __shared__ float ss[8], sq[8];
    int blk = blockIdx.x, tid = threadIdx.x;
    int c = blk >> 3, slab = blk & 7;
    float s = 0.f, q = 0.f;
#pragma unroll
    for (int b = 0; b < Bsz; b++) {
        const float4* t = (const float4*)(g_tmp + (b * Cout + c) * HWp + slab * 2048);
#pragma unroll
        for (int i = 0; i < 2; i++) {
            float4 v = t[tid + i * 256];
            s += v.x + v.y + v.z + v.w;
            q += v.x * v.x + v.y * v.y + v.z * v.z + v.w * v.w;
        }
    }
#pragma unroll
    for (int o = 16; o > 0; o >>= 1) {
        s += __shfl_down_sync(0xffffffff, s, o);
        q += __shfl_down_sync(0xffffffff, q, o);
    }
    if ((tid & 31) == 0) { ss[tid >> 5] = s; sq[tid >> 5] = q; }
    __syncthreads();
    if (tid == 0) {
        float st = 0.f, qt = 0.f;
#pragma unroll
        for (int w = 0; w < 8; w++) { st += ss[w]; qt += sq[w]; }
        g_part[blk * 2] = st;
        g_part[blk * 2 + 1] = qt;
    }
}
__global__ void kC2(const float* __restrict__ gamma, const float* __restrict__ beta)
{
    int c = threadIdx.x;
    float s = 0.f, q = 0.f;
#pragma unroll
    for (int slab = 0; slab < 8; slab++) {
        s += g_part[(c * 8 + slab) * 2];
        q += g_part[(c * 8 + slab) * 2 + 1];
    }
    float n = (float)(Bsz * HWp);
    float mean = s / n;
    float var  = q / n - mean * mean;
    float sc = gamma[c] * rsqrtf(var + 1e-5f);
    g_bn[c] = sc;
    g_bn[Cout + c] = beta[c] - mean * sc;
}

// ---------------------------------------------------------------------------
// kD: elementwise BN affine + ReLU (float4)
// ---------------------------------------------------------------------------
__global__ void kD(float* __restrict__ out)
{
    int i = blockIdx.x * 256 + threadIdx.x;
    const float4* t4 = (const float4*)g_tmp;
    float4 v = t4[i];
    int c = (i >> 12) & 63;
    float sc = g_bn[c], sh = g_bn[Cout + c];
    float4 r;
    r.x = fmaxf(v.x * sc + sh, 0.f);
    r.y = fmaxf(v.y * sc + sh, 0.f);
    r.z = fmaxf(v.z * sc + sh, 0.f);
    r.w = fmaxf(v.w * sc + sh, 0.f);
    ((float4*)out)[i] = r;
}

// ---------------------------------------------------------------------------
extern "C" void kernel_launch(void* const* d_in, const int* in_sizes, int n_in,
                              void* d_out, int out_size)
{
    const float* x      = (const float*)d_in[0];
    const float* conv_w = (const float*)d_in[1];
    const float* off_w  = (const float*)d_in[2];
    const float* off_b  = (const float*)d_in[3];
    const float* mask_w = (const float*)d_in[4];
    const float* mask_b = (const float*)d_in[5];
    const float* gamma  = (const float*)d_in[6];
    const float* beta   = (const float*)d_in[7];
    float* out = (float*)d_out;

    kWB<<<72, 256>>>(conv_w);
    kWA<<<36, 256>>>(off_w, mask_w);
    kA5<<<512, 256>>>(x, off_b, mask_b);
    kB8<<<2048, 128>>>(x);
    kC1<<<512, 256>>>();
    kC2<<<1, 64>>>(gamma, beta);
    kD<<<(Bsz * Cout * HWp / 4) / 256, 256>>>(out);
}

// round 9
// speedup vs baseline: 2.8335x; 1.0461x over previous
#include <cuda_runtime.h>
#include <cstdint>
#include <math.h>

#define HH 128
#define WW 128
#define HWp 16384
#define Cin 64
#define Cout 64
#define Bsz 2
#define NPIX 32768

// ---------------------------------------------------------------------------
// Scratch (no allocations allowed)
// ---------------------------------------------------------------------------
__device__ float  g_om[Bsz*27*HWp];     // 18 raw offsets + 9 sigmoided masks
__device__ float4 g_wB4[9*8*4*32];      // kB B-frags nt-pair packed: [tap][ks][ntp][lane]
__device__ float4 g_wA4[9*8*2*32];      // kA B-frags nt-pair packed
__device__ float  g_tmp[Bsz*Cout*HWp];  // pre-BN conv output (NCHW)
__device__ float  g_part[512*2];        // kC partial sums
__device__ float  g_bn[2*Cout];         // scale, shift

// ---------------------------------------------------------------------------
__device__ __forceinline__ uint32_t cvt_tf32(float v) {
    uint32_t r;
    asm("cvt.rna.tf32.f32 %0, %1;" : "=r"(r) : "f"(v));
    return r;
}
__device__ __forceinline__ void mma_t(float* d,
    uint32_t a0, uint32_t a1, uint32_t a2, uint32_t a3,
    uint32_t b0, uint32_t b1)
{
    asm volatile("mma.sync.aligned.m16n8k8.row.col.f32.tf32.tf32.f32 "
        "{%0,%1,%2,%3}, {%4,%5,%6,%7}, {%8,%9}, {%0,%1,%2,%3};"
        : "+f"(d[0]), "+f"(d[1]), "+f"(d[2]), "+f"(d[3])
        : "r"(a0), "r"(a1), "r"(a2), "r"(a3), "r"(b0), "r"(b1));
}

// ---------------------------------------------------------------------------
// kWB: pack conv_w B-frags, adjacent n-tiles paired into float4 (tf32 hi).
// ---------------------------------------------------------------------------
__global__ void kWB(const float* __restrict__ w)
{
    int i = blockIdx.x * 256 + threadIdx.x;        // 9*8*4*32 = 9216
    if (i >= 9*8*4*32) return;
    int lane = i & 31;
    int ntp  = (i >> 5) & 3;
    int ks   = (i >> 7) & 7;
    int tap  = i >> 10;
    int o0 = (ntp * 2) * 8 + (lane >> 2);
    int o1 = o0 + 8;
    int c0 = ks * 8 + (lane & 3);
    float4 r;
    r.x = __uint_as_float(cvt_tf32(w[o0 * 576 + c0 * 9 + tap]));
    r.y = __uint_as_float(cvt_tf32(w[o0 * 576 + (c0 + 4) * 9 + tap]));
    r.z = __uint_as_float(cvt_tf32(w[o1 * 576 + c0 * 9 + tap]));
    r.w = __uint_as_float(cvt_tf32(w[o1 * 576 + (c0 + 4) * 9 + tap]));
    g_wB4[i] = r;
}

// ---------------------------------------------------------------------------
// kWA: pack offset(18)+mask(9) conv weights (n padded to 32), nt-paired.
// ---------------------------------------------------------------------------
__global__ void kWA(const float* __restrict__ off_w, const float* __restrict__ mask_w)
{
    int i = blockIdx.x * 256 + threadIdx.x;        // 9*8*2*32 = 4608
    if (i >= 9*8*2*32) return;
    int lane = i & 31;
    int ntp  = (i >> 5) & 1;
    int ks   = (i >> 6) & 7;
    int tap  = i >> 9;
    int c0 = ks * 8 + (lane & 3);
    float v[4];
#pragma unroll
    for (int h = 0; h < 2; h++) {
        int o = (ntp * 2 + h) * 8 + (lane >> 2);
        float a = 0.f, bb = 0.f;
        if (o < 18) {
            a  = off_w[o * 576 + c0 * 9 + tap];
            bb = off_w[o * 576 + (c0 + 4) * 9 + tap];
        } else if (o < 27) {
            a  = mask_w[(o - 18) * 576 + c0 * 9 + tap];
            bb = mask_w[(o - 18) * 576 + (c0 + 4) * 9 + tap];
        }
        v[h * 2]     = __uint_as_float(cvt_tf32(a));
        v[h * 2 + 1] = __uint_as_float(cvt_tf32(bb));
    }
    g_wA4[i] = make_float4(v[0], v[1], v[2], v[3]);
}

// ---------------------------------------------------------------------------
// kA5: offset/mask conv as tensor GEMM, K-split x2 across warp pairs.
// ---------------------------------------------------------------------------
__global__ __launch_bounds__(256) void kA5(
    const float* __restrict__ x,
    const float* __restrict__ off_b, const float* __restrict__ mask_b)
{
    __shared__ float red[4][16][32];   // [pg][j][lane]

    int tid = threadIdx.x, wid = tid >> 5, lane = tid & 31;
    int pg = wid & 3, kh = wid >> 2;
    int sidx = blockIdx.x;
    int b = sidx >> 8;
    int y = (sidx >> 1) & 127;
    int p0 = (sidx & 1) * 64 + pg * 16 + (lane >> 2);
    int p1 = p0 + 8;
    const float* xb = x + b * Cin * HWp;

    float acc[4][4];
#pragma unroll
    for (int n = 0; n < 4; n++)
#pragma unroll
        for (int j = 0; j < 4; j++) acc[n][j] = 0.f;

    for (int tap = 0; tap < 9; tap++) {
        int dy = tap / 3 - 1, dx = tap % 3 - 1;
        int yy = y + dy;
        bool vy = ((unsigned)yy < HH);
        int yc = vy ? yy : 0;
        int px0 = p0 + dx, px1 = p1 + dx;
        bool v0 = vy && ((unsigned)px0 < WW);
        bool v1 = vy && ((unsigned)px1 < WW);
        int q0 = v0 ? px0 : 0, q1 = v1 ? px1 : 0;
        const float* xr = xb + yc * WW;

#pragma unroll
        for (int kq = 0; kq < 4; kq++) {
            int ks = kh * 4 + kq;
            int c0 = ks * 8 + (lane & 3);
            const float* pc0 = xr + c0 * HWp;
            const float* pc1 = pc0 + 4 * HWp;
            uint32_t a0 = cvt_tf32(v0 ? pc0[q0] : 0.f);
            uint32_t a1 = cvt_tf32(v1 ? pc0[q1] : 0.f);
            uint32_t a2 = cvt_tf32(v0 ? pc1[q0] : 0.f);
            uint32_t a3 = cvt_tf32(v1 ? pc1[q1] : 0.f);
            const float4* bq = g_wA4 + ((tap * 8 + ks) * 2) * 32 + lane;
#pragma unroll
            for (int ntp = 0; ntp < 2; ntp++) {
                float4 bv = __ldg(bq + ntp * 32);
                mma_t(acc[ntp * 2],     a0, a1, a2, a3,
                      __float_as_uint(bv.x), __float_as_uint(bv.y));
                mma_t(acc[ntp * 2 + 1], a0, a1, a2, a3,
                      __float_as_uint(bv.z), __float_as_uint(bv.w));
            }
        }
    }

    if (kh == 1) {
#pragma unroll
        for (int n = 0; n < 4; n++)
#pragma unroll
            for (int j = 0; j < 4; j++)
                red[pg][n * 4 + j][lane] = acc[n][j];
    }
    __syncthreads();
    if (kh == 0) {
        float* omb = g_om + b * 27 * HWp;
        int yx0 = y * WW + p0, yx1 = y * WW + p1;
#pragma unroll
        for (int nt = 0; nt < 4; nt++) {
            int o = nt * 8 + (lane & 3) * 2;
#pragma unroll
            for (int j = 0; j < 2; j++) {
                int oc = o + j;
                if (oc < 27) {
                    float bias = (oc < 18) ? off_b[oc] : mask_b[oc - 18];
                    float r0 = acc[nt][j]     + red[pg][nt * 4 + j][lane]     + bias;
                    float r1 = acc[nt][j + 2] + red[pg][nt * 4 + j + 2][lane] + bias;
                    if (oc >= 18) {
                        r0 = 1.f / (1.f + expf(-r0));
                        r1 = 1.f / (1.f + expf(-r1));
                    }
                    omb[oc * HWp + yx0] = r0;
                    omb[oc * HWp + yx1] = r1;
                }
            }
        }
    }
}

// ---------------------------------------------------------------------------
// kB9: fused deformable gather + mma tf32 GEMM, K-split x4, single-TF32,
// LDS.64 paired-channel gather, nt-paired LDG.128 B frags, CTA setup table.
// ---------------------------------------------------------------------------
#define TP 72     // words per tile position (64 ch-words + 8 pad; bank step 8)

__global__ __launch_bounds__(128, 7) void kB9(const float* __restrict__ x)
{
    __shared__ float  ts[100 * TP];     // 28800 B tile; reused as reduction buf
    __shared__ float4 sw[9][16];        // bilinear weights (mask-premultiplied)
    __shared__ int    sp[9][16];        // window pos as word offset (pos*TP)
    __shared__ int    allin[9];

    int tid = threadIdx.x, kh = tid >> 5, lane = tid & 31;
    int sidx = blockIdx.x;
    int b = sidx >> 10;
    int y = (sidx >> 3) & 127;
    int p0c = (sidx & 7) * 16;
    int p0 = p0c + (lane >> 2);
    int p1 = p0 + 8;
    const float* xb  = x + b * Cin * HWp;
    const float* omb = g_om + b * 27 * HWp;
    int yx0 = y * WW + p0, yx1 = y * WW + p1;

    if (tid < 9) allin[tid] = 1;
    __syncthreads();

    // ---- stage tile: rows y-2..y+2, cols p0c-2..p0c+17, channel-pair layout ----
    for (int i = tid; i < 64 * 100; i += 128) {
        int c = i / 100;
        int rr = i - c * 100;
        int r = rr / 20, col = rr - r * 20;
        int gy = y - 2 + r, gx = p0c - 2 + col;
        float v = ((unsigned)gy < HH && (unsigned)gx < WW) ? xb[c * HWp + gy * WW + gx] : 0.f;
        int cw = ((c >> 3) << 3) + ((c & 3) << 1) + ((c >> 2) & 1);
        ts[rr * TP + cw] = v;
    }

    // ---- setup table: 144 (tap, px) items ----
    for (int i = tid; i < 144; i += 128) {
        int tap = i >> 4, px = i & 15;
        int p = p0c + px;
        int yx = y * WW + p;
        float ofy = omb[(2 * tap) * HWp + yx];
        float ofx = omb[(2 * tap + 1) * HWp + yx];
        float m   = omb[(18 + tap) * HWp + yx];
        float py  = ofy + (float)y + (float)(tap / 3) - 1.f;
        float pxx = ofx + (float)p + (float)(tap % 3) - 1.f;
        float fy = floorf(py), fx = floorf(pxx);
        int   y0 = (int)fy,    x0 = (int)fx;
        float wy1 = py - fy,  wx1 = pxx - fx;
        float wy0 = 1.f - wy1, wx0 = 1.f - wx1;
        bool vy0 = ((unsigned)y0 < HH),  vy1 = ((unsigned)(y0 + 1) < HH);
        bool vx0 = ((unsigned)x0 < WW),  vx1 = ((unsigned)(x0 + 1) < WW);
        float4 wv;
        wv.x = (vy0 && vx0) ? wy0 * wx0 * m : 0.f;
        wv.y = (vy0 && vx1) ? wy0 * wx1 * m : 0.f;
        wv.z = (vy1 && vx0) ? wy1 * wx0 * m : 0.f;
        wv.w = (vy1 && vx1) ? wy1 * wx1 * m : 0.f;
        sw[tap][px] = wv;
        int ry = y0 - y + 2;
        int rx = x0 - p0c + 2;
        sp[tap][px] = (ry * 20 + rx) * TP;
        if (!(((unsigned)ry <= 3u) && ((unsigned)rx <= 18u))) allin[tap] = 0;
    }
    __syncthreads();

    float acc[8][4];
#pragma unroll
    for (int n = 0; n < 8; n++)
#pragma unroll
        for (int j = 0; j < 4; j++) acc[n][j] = 0.f;

    for (int tap = 0; tap < 9; tap++) {
        if (allin[tap]) {
            // ---- fast path: table + LDS.64 paired-channel gather ----
            float4 wA = sw[tap][lane >> 2];
            float4 wB = sw[tap][8 + (lane >> 2)];
            int baseA = sp[tap][lane >> 2];
            int baseB = sp[tap][8 + (lane >> 2)];
#pragma unroll
            for (int kq = 0; kq < 2; kq++) {
                int ks = kh * 2 + kq;
                int cw = (ks << 3) + ((lane & 3) << 1);
                const float2* tA = (const float2*)(ts + baseA + cw);
                const float2* tB = (const float2*)(ts + baseB + cw);
                float2 A0 = tA[0], A1 = tA[TP/2], A2 = tA[10*TP], A3 = tA[10*TP + TP/2];
                float2 B0 = tB[0], B1 = tB[TP/2], B2 = tB[10*TP], B3 = tB[10*TP + TP/2];

                float va0 = wA.x*A0.x + wA.y*A1.x + wA.z*A2.x + wA.w*A3.x;
                float va1 = wB.x*B0.x + wB.y*B1.x + wB.z*B2.x + wB.w*B3.x;
                float va2 = wA.x*A0.y + wA.y*A1.y + wA.z*A2.y + wA.w*A3.y;
                float va3 = wB.x*B0.y + wB.y*B1.y + wB.z*B2.y + wB.w*B3.y;

                uint32_t h0 = cvt_tf32(va0);
                uint32_t h1 = cvt_tf32(va1);
                uint32_t h2 = cvt_tf32(va2);
                uint32_t h3 = cvt_tf32(va3);

                const float4* bq = g_wB4 + ((tap * 8 + ks) * 4) * 32 + lane;
#pragma unroll
                for (int ntp = 0; ntp < 4; ntp++) {
                    float4 bv = __ldg(bq + ntp * 32);
                    mma_t(acc[ntp * 2],     h0, h1, h2, h3,
                          __float_as_uint(bv.x), __float_as_uint(bv.y));
                    mma_t(acc[ntp * 2 + 1], h0, h1, h2, h3,
                          __float_as_uint(bv.z), __float_as_uint(bv.w));
                }
            }
        } else {
            // ---- fallback: exact global gather (rare) ----
            float wA[4], wB[4];
            int   oA[4], oB[4];
#pragma unroll
            for (int s = 0; s < 2; s++) {
                int yx = s ? yx1 : yx0;
                int px = s ? p1 : p0;
                float ofy = omb[(2 * tap) * HWp + yx];
                float ofx = omb[(2 * tap + 1) * HWp + yx];
                float m   = omb[(18 + tap) * HWp + yx];
                float py = ofy + (float)y  + (float)(tap / 3) - 1.f;
                float pxx = ofx + (float)px + (float)(tap % 3) - 1.f;
                float fy = floorf(py), fx = floorf(pxx);
                int   y0 = (int)fy,    x0 = (int)fx;
                float wy1 = py - fy,  wx1 = pxx - fx;
                float wy0 = 1.f - wy1, wx0 = 1.f - wx1;
                bool vy0 = ((unsigned)y0 < HH),      vy1 = ((unsigned)(y0 + 1) < HH);
                bool vx0 = ((unsigned)x0 < WW),      vx1 = ((unsigned)(x0 + 1) < WW);
                int cy0 = min(max(y0, 0), HH - 1),   cy1 = min(max(y0 + 1, 0), HH - 1);
                int cx0 = min(max(x0, 0), WW - 1),   cx1 = min(max(x0 + 1, 0), WW - 1);
                float* wp = s ? wB : wA;
                int*   op = s ? oB : oA;
                wp[0] = (vy0 && vx0) ? wy0 * wx0 * m : 0.f;
                wp[1] = (vy0 && vx1) ? wy0 * wx1 * m : 0.f;
                wp[2] = (vy1 && vx0) ? wy1 * wx0 * m : 0.f;
                wp[3] = (vy1 && vx1) ? wy1 * wx1 * m : 0.f;
                op[0] = cy0 * WW + cx0; op[1] = cy0 * WW + cx1;
                op[2] = cy1 * WW + cx0; op[3] = cy1 * WW + cx1;
            }
#pragma unroll
            for (int kq = 0; kq < 2; kq++) {
                int ks = kh * 2 + kq;
                int c0 = ks * 8 + (lane & 3);
                const float* pc0 = xb + c0 * HWp;
                const float* pc1 = pc0 + 4 * HWp;

                float va0 = wA[0]*pc0[oA[0]] + wA[1]*pc0[oA[1]] + wA[2]*pc0[oA[2]] + wA[3]*pc0[oA[3]];
                float va1 = wB[0]*pc0[oB[0]] + wB[1]*pc0[oB[1]] + wB[2]*pc0[oB[2]] + wB[3]*pc0[oB[3]];
                float va2 = wA[0]*pc1[oA[0]] + wA[1]*pc1[oA[1]] + wA[2]*pc1[oA[2]] + wA[3]*pc1[oA[3]];
                float va3 = wB[0]*pc1[oB[0]] + wB[1]*pc1[oB[1]] + wB[2]*pc1[oB[2]] + wB[3]*pc1[oB[3]];

                uint32_t h0 = cvt_tf32(va0);
                uint32_t h1 = cvt_tf32(va1);
                uint32_t h2 = cvt_tf32(va2);
                uint32_t h3 = cvt_tf32(va3);

                const float4* bq = g_wB4 + ((tap * 8 + ks) * 4) * 32 + lane;
#pragma unroll
                for (int ntp = 0; ntp < 4; ntp++) {
                    float4 bv = __ldg(bq + ntp * 32);
                    mma_t(acc[ntp * 2],     h0, h1, h2, h3,
                          __float_as_uint(bv.x), __float_as_uint(bv.y));
                    mma_t(acc[ntp * 2 + 1], h0, h1, h2, h3,
                          __float_as_uint(bv.z), __float_as_uint(bv.w));
                }
            }
        }
    }

    // ---- cross-warp K reduction (reuse tile smem; conflict-free) ----
    __syncthreads();                 // done reading tile
    float* red = ts;                 // [w][j][lane]
    if (kh != 0) {
#pragma unroll
        for (int n = 0; n < 8; n++)
#pragma unroll
            for (int j = 0; j < 4; j++)
                red[(kh - 1) * 1024 + (n * 4 + j) * 32 + lane] = acc[n][j];
    }
    __syncthreads();
    if (kh == 0) {
        float* tb = g_tmp + b * Cout * HWp + y * WW;
#pragma unroll
        for (int nt = 0; nt < 8; nt++) {
            int o = nt * 8 + (lane & 3) * 2;
            float r0 = acc[nt][0], r1 = acc[nt][1], r2 = acc[nt][2], r3 = acc[nt][3];
#pragma unroll
            for (int w = 0; w < 3; w++) {
                r0 += red[w * 1024 + (nt * 4 + 0) * 32 + lane];
                r1 += red[w * 1024 + (nt * 4 + 1) * 32 + lane];
                r2 += red[w * 1024 + (nt * 4 + 2) * 32 + lane];
                r3 += red[w * 1024 + (nt * 4 + 3) * 32 + lane];
            }
            tb[o * HWp + p0]       = r0;
            tb[(o + 1) * HWp + p0] = r1;
            tb[o * HWp + p1]       = r2;
            tb[(o + 1) * HWp + p1] = r3;
        }
    }
}

// ---------------------------------------------------------------------------
// kC1: partial per-channel sums (512 blocks), kC2: finalize
// ---------------------------------------------------------------------------
__global__ __launch_bounds__(256) void kC1()
{
    __shared__ float ss[8], sq[8];
    int blk = blockIdx.x, tid = threadIdx.x;
    int c = blk >> 3, slab = blk & 7;
    float s = 0.f, q = 0.f;
#pragma unroll
    for (int b = 0; b < Bsz; b++) {
        const float4* t = (const float4*)(g_tmp + (b * Cout + c) * HWp + slab * 2048);
#pragma unroll
        for (int i = 0; i < 2; i++) {
            float4 v = t[tid + i * 256];
            s += v.x + v.y + v.z + v.w;
            q += v.x * v.x + v.y * v.y + v.z * v.z + v.w * v.w;
        }
    }
#pragma unroll
    for (int o = 16; o > 0; o >>= 1) {
        s += __shfl_down_sync(0xffffffff, s, o);
        q += __shfl_down_sync(0xffffffff, q, o);
    }
    if ((tid & 31) == 0) { ss[tid >> 5] = s; sq[tid >> 5] = q; }
    __syncthreads();
    if (tid == 0) {
        float st = 0.f, qt = 0.f;
#pragma unroll
        for (int w = 0; w < 8; w++) { st += ss[w]; qt += sq[w]; }
        g_part[blk * 2] = st;
        g_part[blk * 2 + 1] = qt;
    }
}
__global__ void kC2(const float* __restrict__ gamma, const float* __restrict__ beta)
{
    int c = threadIdx.x;
    float s = 0.f, q = 0.f;
#pragma unroll
    for (int slab = 0; slab < 8; slab++) {
        s += g_part[(c * 8 + slab) * 2];
        q += g_part[(c * 8 + slab) * 2 + 1];
    }
    float n = (float)(Bsz * HWp);
    float mean = s / n;
    float var  = q / n - mean * mean;
    float sc = gamma[c] * rsqrtf(var + 1e-5f);
    g_bn[c] = sc;
    g_bn[Cout + c] = beta[c] - mean * sc;
}

// ---------------------------------------------------------------------------
// kD: elementwise BN affine + ReLU (float4)
// ---------------------------------------------------------------------------
__global__ void kD(float* __restrict__ out)
{
    int i = blockIdx.x * 256 + threadIdx.x;
    const float4* t4 = (const float4*)g_tmp;
    float4 v = t4[i];
    int c = (i >> 12) & 63;
    float sc = g_bn[c], sh = g_bn[Cout + c];
    float4 r;
    r.x = fmaxf(v.x * sc + sh, 0.f);
    r.y = fmaxf(v.y * sc + sh, 0.f);
    r.z = fmaxf(v.z * sc + sh, 0.f);
    r.w = fmaxf(v.w * sc + sh, 0.f);
    ((float4*)out)[i] = r;
}

// ---------------------------------------------------------------------------
extern "C" void kernel_launch(void* const* d_in, const int* in_sizes, int n_in,
                              void* d_out, int out_size)
{
    const float* x      = (const float*)d_in[0];
    const float* conv_w = (const float*)d_in[1];
    const float* off_w  = (const float*)d_in[2];
    const float* off_b  = (const float*)d_in[3];
    const float* mask_w = (const float*)d_in[4];
    const float* mask_b = (const float*)d_in[5];
    const float* gamma  = (const float*)d_in[6];
    const float* beta   = (const float*)d_in[7];
    float* out = (float*)d_out;

    kWB<<<36, 256>>>(conv_w);
    kWA<<<18, 256>>>(off_w, mask_w);
    kA5<<<512, 256>>>(x, off_b, mask_b);
    kB9<<<2048, 128>>>(x);
    kC1<<<512, 256>>>();
    kC2<<<1, 64>>>(gamma, beta);
    kD<<<(Bsz * Cout * HWp / 4) / 256, 256>>>(out);
}